// round 10
// baseline (speedup 1.0000x reference)
#include <cuda_runtime.h>
#include <cuda_fp16.h>
#include <cstdint>

#define CC 256
#define HWC 3136
#define MM 100352
#define NTILE 784
#define NTH 256
#define STRA 40                 /* halfs per smem row (80B, conflict-free ldmatrix) */
#define STG_AH 0
#define STG_AM 10240
#define STG_BH 20480
#define STG_BM 30720
#define STG_SZ 40960
#define SO_STG 8192
#define SMEM_T (SO_STG + 2*STG_SZ)   /* 90112 */
#define INV2048 (1.0f/2048.0f)

/* GEMM2 (IMMA) stage layout: A u8 [128m][48B], B1/B2 s8 [128n][48B] */
#define G2_B1 6144
#define G2_B2 12288
#define G2_STG 18432

// -------------------- device scratch --------------------
__device__ __align__(16) float  g_buf[(size_t)CC*MM];
__device__ __align__(16) __half ut_hi_d[CC*CC], ut_mid_d[CC*CC];   // GEMM1 B [j][c]
__device__ __align__(16) signed char d1_d[CC*CC], d2_d[CC*CC];     // GEMM2 B digits [c][j]
__device__ float    lam_d[CC];
__device__ float    chsum_d[CC];
__device__ unsigned gmax_d[CC], gmin_d[CC];
__device__ float    mn_d[CC], s_d[CC], dmin_d[CC], scale_d[CC], inv_d[CC], cvv_d[CC];
__device__ float    qsum_d[CC], bias_d[CC], same_d[CC];

// -------------------- helpers --------------------
__device__ __forceinline__ void cp16(uint32_t sdst, const void* g) {
    asm volatile("cp.async.ca.shared.global [%0], [%1], 16;" :: "r"(sdst), "l"(g) : "memory");
}
__device__ __forceinline__ void cp_commit() { asm volatile("cp.async.commit_group;" ::: "memory"); }
__device__ __forceinline__ void cp_wait0()  { asm volatile("cp.async.wait_group 0;" ::: "memory"); }

__device__ __forceinline__ void ldsm4(unsigned* r, uint32_t addr) {
    asm volatile("ldmatrix.sync.aligned.m8n8.x4.shared.b16 {%0,%1,%2,%3}, [%4];"
        : "=r"(r[0]), "=r"(r[1]), "=r"(r[2]), "=r"(r[3]) : "r"(addr));
}
__device__ __forceinline__ void mma16816(float* d, const unsigned* a, const unsigned* b) {
    asm volatile("mma.sync.aligned.m16n8k16.row.col.f32.f16.f16.f32 "
        "{%0,%1,%2,%3}, {%4,%5,%6,%7}, {%8,%9}, {%0,%1,%2,%3};"
        : "+f"(d[0]), "+f"(d[1]), "+f"(d[2]), "+f"(d[3])
        : "r"(a[0]), "r"(a[1]), "r"(a[2]), "r"(a[3]), "r"(b[0]), "r"(b[1]));
}
__device__ __forceinline__ void imma(int* d, const unsigned* a, const unsigned* b) {
    asm volatile("mma.sync.aligned.m16n8k32.row.col.s32.u8.s8.s32 "
        "{%0,%1,%2,%3}, {%4,%5,%6,%7}, {%8,%9}, {%0,%1,%2,%3};"
        : "+r"(d[0]), "+r"(d[1]), "+r"(d[2]), "+r"(d[3])
        : "r"(a[0]), "r"(a[1]), "r"(a[2]), "r"(a[3]), "r"(b[0]), "r"(b[1]));
}
__device__ __forceinline__ unsigned encf(float f) {
    unsigned u = __float_as_uint(f);
    return (u & 0x80000000u) ? ~u : (u | 0x80000000u);
}
__device__ __forceinline__ float decf(unsigned u) {
    unsigned b = (u & 0x80000000u) ? (u & 0x7FFFFFFFu) : ~u;
    return __uint_as_float(b);
}
__device__ __forceinline__ float quant1(float g, float s, float dm, float sc, float iv,
                                        float cv, float sm) {
    float val = fminf(fmaxf(g - s, -cv), cv);
    float qq  = rintf((val - dm) * sc) * iv + dm;
    return (sm > 0.5f) ? val : qq;
}

// -------------------- prep: split u^T into fp16 hi/mid (scaled), zero accumulators ----
__global__ void prep_k(const float* __restrict__ u) {
    int t = threadIdx.x, b = blockIdx.x;
    if (b < CC) {
        float val = u[(size_t)b*CC + t];          // u[c=b][j=t]
        __half h = __float2half_rn(val);
        __half e = __float2half_rn((val - __half2float(h)) * 2048.0f);
        ut_hi_d[t*CC + b] = h;  ut_mid_d[t*CC + b] = e;   // [j][c] for GEMM1 B
    } else {
        chsum_d[t] = 0.0f; qsum_d[t] = 0.0f;
        gmax_d[t] = 0u; gmin_d[t] = 0xFFFFFFFFu;
    }
}

// -------------------- GEMM1 (R7-proven): g = u^T relu(x), 3-term fp16 split ----
__global__ void __launch_bounds__(NTH)
gemm1_k(const float* __restrict__ X)
{
    extern __shared__ char smem[];
    const uint32_t sb = (uint32_t)__cvta_generic_to_shared(smem);
    const int tid = threadIdx.x;
    const int lane = tid & 31, w = tid >> 5;
    const int m0 = blockIdx.x * 128;
    const int by = blockIdx.y;

    const int mg = tid & 15, cp = tid >> 4;
    const int mrow = m0 + mg*8;
    int nimg = mrow / HWC;
    size_t abase = (size_t)nimg*(CC*HWC) + (size_t)(mrow - nimg*HWC);

    float v[2][8];

    auto loadA = [&](int kc) {
        #pragma unroll
        for (int cc = 0; cc < 2; cc++) {
            int c = kc*32 + cp*2 + cc;
            const float4* p = (const float4*)(X + abase + (size_t)c*HWC);
            float4 q0 = p[0], q1 = p[1];
            v[cc][0]=q0.x; v[cc][1]=q0.y; v[cc][2]=q0.z; v[cc][3]=q0.w;
            v[cc][4]=q1.x; v[cc][5]=q1.y; v[cc][6]=q1.z; v[cc][7]=q1.w;
        }
    };
    auto procA = [&](int kc, int st) {
        char* base = smem + SO_STG + st*STG_SZ;
        #pragma unroll
        for (int cc = 0; cc < 2; cc++) {
            int c = kc*32 + cp*2 + cc;
            float s = 0.f;
            #pragma unroll
            for (int i = 0; i < 8; i++) { v[cc][i] = fmaxf(v[cc][i], 0.f); s += v[cc][i]; }
            s += __shfl_xor_sync(~0u, s, 1); s += __shfl_xor_sync(~0u, s, 2);
            s += __shfl_xor_sync(~0u, s, 4); s += __shfl_xor_sync(~0u, s, 8);
            if (by == 0 && (lane & 15) == 0) atomicAdd(&chsum_d[c], s);
        }
        #pragma unroll
        for (int i = 0; i < 8; i++) {
            __half h0 = __float2half_rn(v[0][i]);
            __half h1 = __float2half_rn(v[1][i]);
            __half e0 = __float2half_rn((v[0][i] - __half2float(h0)) * 2048.0f);
            __half e1 = __float2half_rn((v[1][i] - __half2float(h1)) * 2048.0f);
            uint32_t off = (uint32_t)(((mg*8 + i)*STRA + cp*2) * 2);
            *(__half2*)(base + STG_AH + off) = __halves2half2(h0, h1);
            *(__half2*)(base + STG_AM + off) = __halves2half2(e0, e1);
        }
    };
    auto prodB = [&](int kc, int st) {
        #pragma unroll
        for (int i = 0; i < 4; i++) {
            int ui = tid + i*NTH;
            int ish = (ui < 512);
            int r = (ui & 511) >> 2;
            int q = ui & 3;
            uint32_t dst = sb + SO_STG + st*STG_SZ + (ish ? STG_BH : STG_BM)
                         + (uint32_t)(r*80 + q*16);
            const __half* s = (ish ? ut_hi_d : ut_mid_d) + (size_t)(by*128 + r)*CC + kc*32 + q*8;
            cp16(dst, s);
        }
    };

    float acch[2][8][4] = {};
    float accm[2][8][4] = {};
    const int wm = (w & 3) * 32;
    const int wn = (w >> 2) * 64;

    prodB(0, 0); cp_commit();
    loadA(0);
    procA(0, 0);

    const int arow = (lane & 15);
    const int asel = (lane >> 4) << 3;
    const int brow = (lane & 7) + ((lane >> 4) << 3);
    const int bsel = ((lane >> 3) & 1) << 3;

    for (int kc = 0; kc < 8; kc++) {
        const int st = kc & 1;
        if (kc < 7) loadA(kc + 1);
        cp_wait0();
        __syncthreads();

        const uint32_t ahb = sb + SO_STG + st*STG_SZ + STG_AH;
        const uint32_t bhb = sb + SO_STG + st*STG_SZ + STG_BH;
        #pragma unroll
        for (int ks = 0; ks < 2; ks++) {
            const int kb = ks*16;
            unsigned ah[2][4], am[2][4];
            #pragma unroll
            for (int mt = 0; mt < 2; mt++) {
                uint32_t ra = ahb + (uint32_t)(((wm + mt*16 + arow)*STRA + kb + asel) * 2);
                ldsm4(ah[mt], ra);
                ldsm4(am[mt], ra + (STG_AM - STG_AH));
            }
            #pragma unroll
            for (int ng = 0; ng < 4; ng++) {
                uint32_t rb = bhb + (uint32_t)(((wn + ng*16 + brow)*STRA + kb + bsel) * 2);
                unsigned bh[4], bm[4];
                ldsm4(bh, rb);
                ldsm4(bm, rb + (STG_BM - STG_BH));
                #pragma unroll
                for (int mt = 0; mt < 2; mt++) {
                    mma16816(acch[mt][ng*2],     ah[mt], bh);
                    mma16816(acch[mt][ng*2 + 1], ah[mt], bh + 2);
                    mma16816(accm[mt][ng*2],     ah[mt], bm);
                    mma16816(accm[mt][ng*2 + 1], ah[mt], bm + 2);
                    mma16816(accm[mt][ng*2],     am[mt], bh);
                    mma16816(accm[mt][ng*2 + 1], am[mt], bh + 2);
                }
            }
        }
        if (kc < 7) { procA(kc + 1, st ^ 1); prodB(kc + 1, st ^ 1); cp_commit(); }
    }
    __syncthreads();

    float* scr = (float*)(smem + SO_STG) + w * (64*36);
    #pragma unroll
    for (int mt = 0; mt < 2; mt++)
        #pragma unroll
        for (int nt = 0; nt < 8; nt++)
            #pragma unroll
            for (int i = 0; i < 4; i++) {
                int nl = nt*8 + (lane & 3)*2 + (i & 1);
                int ml = mt*16 + (lane >> 2) + ((i >> 1) << 3);
                scr[nl*36 + ml] = acch[mt][nt][i] + accm[mt][nt][i] * INV2048;
            }
    __syncwarp();

    #pragma unroll 4
    for (int r = 0; r < 64; r++) {
        int j = by*128 + wn + r;
        float val = scr[r*36 + lane];
        float mx = val, mn = val;
        #pragma unroll
        for (int d = 1; d < 32; d <<= 1) {
            mx = fmaxf(mx, __shfl_xor_sync(~0u, mx, d));
            mn = fminf(mn, __shfl_xor_sync(~0u, mn, d));
        }
        g_buf[(size_t)j*MM + m0 + wm + lane] = val;
        if (lane == 0) {
            atomicMax(&gmax_d[j], encf(mx));
            atomicMin(&gmin_d[j], encf(mn));
        }
    }
}

// -------------------- GEMM2 (IMMA): out = lam_c*(sum n*d1 + sum n*d2 /128) + bias ----
__global__ void __launch_bounds__(NTH)
gemm2_k(float* __restrict__ OUT)
{
    extern __shared__ char smem[];
    const uint32_t sb = (uint32_t)__cvta_generic_to_shared(smem);
    const int tid = threadIdx.x;
    const int lane = tid & 31, w = tid >> 5;
    const int m0 = blockIdx.x * 128;
    const int by = blockIdx.y;

    float* ps = (float*)smem;
    ps[tid]        = s_d[tid];
    ps[256 + tid]  = dmin_d[tid];
    ps[512 + tid]  = scale_d[tid];
    ps[768 + tid]  = cvv_d[tid];
    ps[1024 + tid] = bias_d[tid];
    ps[1280 + tid] = lam_d[tid];
    __syncthreads();

    const int mg = tid & 15, cp = tid >> 4;
    const int mrow = m0 + mg*8;
    float v[2][8];

    auto loadA = [&](int kc) {
        #pragma unroll
        for (int cc = 0; cc < 2; cc++) {
            int c = kc*32 + cp*2 + cc;
            const float4* p = (const float4*)(g_buf + (size_t)c*MM + mrow);
            float4 q0 = p[0], q1 = p[1];
            v[cc][0]=q0.x; v[cc][1]=q0.y; v[cc][2]=q0.z; v[cc][3]=q0.w;
            v[cc][4]=q1.x; v[cc][5]=q1.y; v[cc][6]=q1.z; v[cc][7]=q1.w;
        }
    };
    auto procA = [&](int kc, int st) {
        char* base = smem + SO_STG + st*G2_STG;
        #pragma unroll
        for (int cc = 0; cc < 2; cc++) {
            int c = kc*32 + cp*2 + cc;
            float S=ps[c], DM=ps[256+c], SC=ps[512+c], CV=ps[768+c];
            #pragma unroll
            for (int i = 0; i < 8; i++) {
                float val = fminf(fmaxf(v[cc][i] - S, -CV), CV);
                v[cc][i] = rintf((val - DM) * SC);   // integer level 0..255
            }
        }
        #pragma unroll
        for (int i = 0; i < 8; i++) {
            unsigned n0 = (unsigned)(int)v[0][i];
            unsigned n1 = (unsigned)(int)v[1][i];
            *(unsigned short*)(base + (mg*8 + i)*48 + cp*2) =
                (unsigned short)(n0 | (n1 << 8));
        }
    };
    auto prodB = [&](int kc, int st) {
        #pragma unroll
        for (int i = 0; i < 2; i++) {
            int idx = tid + i*NTH;                // 0..511
            int dig = idx >> 8;
            int r = (idx & 255) >> 1;
            int q = idx & 1;
            uint32_t dst = sb + SO_STG + st*G2_STG + (dig ? G2_B2 : G2_B1)
                         + (uint32_t)(r*48 + q*16);
            const signed char* s = (dig ? d2_d : d1_d)
                         + (size_t)(by*128 + r)*CC + kc*32 + q*16;
            cp16(dst, s);
        }
    };

    int acc1[2][8][4] = {};
    int acc2[2][8][4] = {};
    const int wm = (w & 3) * 32;
    const int wn = (w >> 2) * 64;
    const int tq = lane >> 2;
    const int q4 = (lane & 3) * 4;

    prodB(0, 0); cp_commit();
    loadA(0);
    procA(0, 0);

    for (int kc = 0; kc < 8; kc++) {
        const int st = kc & 1;
        if (kc < 7) loadA(kc + 1);
        cp_wait0();
        __syncthreads();

        const char* As = smem + SO_STG + st*G2_STG;
        const char* B1 = As + G2_B1;
        const char* B2 = As + G2_B2;

        unsigned a[2][4];
        #pragma unroll
        for (int mt = 0; mt < 2; mt++) {
            int base = (wm + mt*16 + tq)*48 + q4;
            a[mt][0] = *(const unsigned*)(As + base);
            a[mt][1] = *(const unsigned*)(As + base + 8*48);
            a[mt][2] = *(const unsigned*)(As + base + 16);
            a[mt][3] = *(const unsigned*)(As + base + 8*48 + 16);
        }
        #pragma unroll
        for (int ng = 0; ng < 8; ng++) {
            int bb = (wn + ng*8 + tq)*48 + q4;
            unsigned b1[2] = { *(const unsigned*)(B1 + bb), *(const unsigned*)(B1 + bb + 16) };
            unsigned b2[2] = { *(const unsigned*)(B2 + bb), *(const unsigned*)(B2 + bb + 16) };
            #pragma unroll
            for (int mt = 0; mt < 2; mt++) {
                imma(acc1[mt][ng], a[mt], b1);
                imma(acc2[mt][ng], a[mt], b2);
            }
        }
        if (kc < 7) { procA(kc + 1, st ^ 1); prodB(kc + 1, st ^ 1); cp_commit(); }
    }
    __syncthreads();

    float* scr = (float*)(smem + SO_STG) + w * (64*36);
    #pragma unroll
    for (int mt = 0; mt < 2; mt++)
        #pragma unroll
        for (int nt = 0; nt < 8; nt++)
            #pragma unroll
            for (int i = 0; i < 4; i++) {
                int nl = nt*8 + (lane & 3)*2 + (i & 1);
                int ml = mt*16 + (lane >> 2) + ((i >> 1) << 3);
                scr[nl*36 + ml] = (float)acc1[mt][nt][i]
                                + (float)acc2[mt][nt][i] * 0.0078125f;
            }
    __syncwarp();

    int mstart = m0 + wm;
    int nimg = mstart / HWC;
    size_t base = (size_t)nimg*(CC*HWC) + (size_t)(mstart - nimg*HWC);
    #pragma unroll 4
    for (int r = 0; r < 64; r++) {
        int c = by*128 + wn + r;
        OUT[base + (size_t)c*HWC + lane] = ps[1280 + c] * scr[r*36 + lane] + ps[1024 + c];
    }
}

// -------------------- mid: mn, s, clip, quant params --------------------
__global__ void mid_k(const float* __restrict__ u, const float* __restrict__ cv,
                      const int* __restrict__ abw) {
    __shared__ float mns[CC];
    int t = threadIdx.x;
    float mn = chsum_d[t] * (1.0f / (float)MM);
    mn_d[t] = mn; mns[t] = mn;
    __syncthreads();
    float s = 0.0f;
    #pragma unroll 8
    for (int c = 0; c < CC; c++) s += u[(size_t)c*CC + t] * mns[c];
    s_d[t] = s;
    float c = cv[t]; cvv_d[t] = c;
    int ab = abw ? *abw : 8;
    float dmax = fminf(fmaxf(decf(gmax_d[t]) - s, -c), c);
    float dmin = fminf(fmaxf(decf(gmin_d[t]) - s, -c), c);
    int same = (dmax == dmin) || (ab >= 17);
    float rng = same ? 1.0f : (dmax - dmin);
    float levels = (float)((1 << (same ? 8 : ab)) - 1);
    same_d[t]  = same ? 1.0f : 0.0f;
    dmin_d[t]  = dmin;
    scale_d[t] = levels / rng;
    inv_d[t]   = rng / levels;
}

// -------------------- wsplit: w = u*iv -> per-row lambda + 2 s8 digits ----
__global__ void wsplit_k(const float* __restrict__ u) {
    __shared__ float red[8];
    __shared__ float lsh;
    int c = blockIdx.x, j = threadIdx.x;
    int lane = j & 31, wid = j >> 5;
    float wv = u[(size_t)c*CC + j] * inv_d[j];
    float m = fabsf(wv);
    #pragma unroll
    for (int d = 1; d < 32; d <<= 1) m = fmaxf(m, __shfl_xor_sync(~0u, m, d));
    if (lane == 0) red[wid] = m;
    __syncthreads();
    if (j == 0) {
        float mx = red[0];
        #pragma unroll
        for (int i = 1; i < 8; i++) mx = fmaxf(mx, red[i]);
        lsh = fmaxf(mx * (1.0f/127.0f), 1e-30f);
    }
    __syncthreads();
    float lam = lsh;
    float t = wv / lam;
    int d1 = (int)lrintf(t);
    d1 = min(127, max(-127, d1));
    int d2 = (int)lrintf((t - (float)d1) * 128.0f);
    d2 = min(127, max(-127, d2));
    d1_d[(size_t)c*CC + j] = (signed char)d1;
    d2_d[(size_t)c*CC + j] = (signed char)d2;
    if (j == 0) lam_d[c] = lam;
}

// -------------------- qsum: MLP-4 quant reduction --------------------
__global__ void __launch_bounds__(128) qsum_k() {
    __shared__ float red[4];
    int j = blockIdx.y;
    float s = s_d[j], dm = dmin_d[j], sc = scale_d[j], iv = inv_d[j],
          cv = cvv_d[j], smf = same_d[j];
    size_t base = (size_t)j*MM + (size_t)blockIdx.x*2048 + threadIdx.x*4;
    float4 v0 = *(const float4*)(g_buf + base);
    float4 v1 = *(const float4*)(g_buf + base + 512);
    float4 v2 = *(const float4*)(g_buf + base + 1024);
    float4 v3 = *(const float4*)(g_buf + base + 1536);
    float sum = quant1(v0.x,s,dm,sc,iv,cv,smf) + quant1(v0.y,s,dm,sc,iv,cv,smf)
              + quant1(v0.z,s,dm,sc,iv,cv,smf) + quant1(v0.w,s,dm,sc,iv,cv,smf)
              + quant1(v1.x,s,dm,sc,iv,cv,smf) + quant1(v1.y,s,dm,sc,iv,cv,smf)
              + quant1(v1.z,s,dm,sc,iv,cv,smf) + quant1(v1.w,s,dm,sc,iv,cv,smf)
              + quant1(v2.x,s,dm,sc,iv,cv,smf) + quant1(v2.y,s,dm,sc,iv,cv,smf)
              + quant1(v2.z,s,dm,sc,iv,cv,smf) + quant1(v2.w,s,dm,sc,iv,cv,smf)
              + quant1(v3.x,s,dm,sc,iv,cv,smf) + quant1(v3.y,s,dm,sc,iv,cv,smf)
              + quant1(v3.z,s,dm,sc,iv,cv,smf) + quant1(v3.w,s,dm,sc,iv,cv,smf);
    #pragma unroll
    for (int d = 1; d < 32; d <<= 1) sum += __shfl_xor_sync(~0u, sum, d);
    int lane = threadIdx.x & 31, wid = threadIdx.x >> 5;
    if (lane == 0) red[wid] = sum;
    __syncthreads();
    if (threadIdx.x == 0)
        atomicAdd(&qsum_d[j], red[0] + red[1] + red[2] + red[3]);
}

// -------------------- bias2[c] = mn[c] + sum_j u[c][j]*(dmin[j] - qmean[j]) ----
__global__ void bias_k(const float* __restrict__ u) {
    __shared__ float dq[CC];
    int t = threadIdx.x;
    dq[t] = dmin_d[t] - qsum_d[t] * (1.0f / (float)MM);
    __syncthreads();
    float b = 0.0f;
    #pragma unroll 8
    for (int j = 0; j < CC; j++) b += u[(size_t)t*CC + j] * dq[j];
    bias_d[t] = mn_d[t] + b;
}

// -------------------- launcher --------------------
extern "C" void kernel_launch(void* const* d_in, const int* in_sizes, int n_in,
                              void* d_out, int out_size) {
    const float* x  = (const float*)d_in[0];
    const float* u  = (const float*)d_in[1];
    const float* cv = (const float*)d_in[2];
    const int*   ab = (n_in > 3) ? (const int*)d_in[3] : nullptr;
    float* out = (float*)d_out;
    (void)in_sizes; (void)out_size;

    cudaFuncSetAttribute(gemm1_k, cudaFuncAttributeMaxDynamicSharedMemorySize, SMEM_T);
    cudaFuncSetAttribute(gemm2_k, cudaFuncAttributeMaxDynamicSharedMemorySize, SMEM_T);

    prep_k<<<CC + 1, CC>>>(u);
    gemm1_k<<<dim3(NTILE, 2), NTH, SMEM_T>>>(x);
    mid_k<<<1, CC>>>(u, cv, ab);
    wsplit_k<<<CC, CC>>>(u);
    qsum_k<<<dim3(49, CC), 128>>>();
    bias_k<<<1, CC>>>(u);
    gemm2_k<<<dim3(NTILE, 2), NTH, SMEM_T>>>(out);
}

// round 11
// speedup vs baseline: 1.3029x; 1.3029x over previous
#include <cuda_runtime.h>
#include <cuda_fp16.h>
#include <cstdint>

#define CC 256
#define HWC 3136
#define MM 100352
#define NTILE 784
#define NTH 256
#define STRA 40                 /* halfs per smem row (80B, conflict-free ldmatrix) */
#define STG_AH 0
#define STG_AM 10240
#define STG_BH 20480
#define STG_BM 30720
#define STG_SZ 40960
#define SO_STG 8192
#define SMEM_T (SO_STG + 2*STG_SZ)   /* 90112 */
#define INV2048 (1.0f/2048.0f)
#define INV1024 (1.0f/1024.0f)

// -------------------- device scratch --------------------
__device__ __align__(16) float  g_buf[(size_t)CC*MM];
__device__ __align__(16) __half ut_hi_d[CC*CC], ut_mid_d[CC*CC];   // GEMM1 B [j][c]
__device__ __align__(16) __half w_hi_d[CC*CC];                     // GEMM2 B [c][j] = fp16(u*iv*1024)
__device__ float    chsum_d[CC];
__device__ unsigned gmax_d[CC], gmin_d[CC];
__device__ float    mn_d[CC], s_d[CC], dmin_d[CC], scale_d[CC], inv_d[CC], cvv_d[CC];
__device__ float    qsum_d[CC], bias_d[CC], same_d[CC];

// -------------------- helpers --------------------
__device__ __forceinline__ void cp16(uint32_t sdst, const void* g) {
    asm volatile("cp.async.ca.shared.global [%0], [%1], 16;" :: "r"(sdst), "l"(g) : "memory");
}
__device__ __forceinline__ void cp_commit() { asm volatile("cp.async.commit_group;" ::: "memory"); }
__device__ __forceinline__ void cp_wait0()  { asm volatile("cp.async.wait_group 0;" ::: "memory"); }

__device__ __forceinline__ void ldsm4(unsigned* r, uint32_t addr) {
    asm volatile("ldmatrix.sync.aligned.m8n8.x4.shared.b16 {%0,%1,%2,%3}, [%4];"
        : "=r"(r[0]), "=r"(r[1]), "=r"(r[2]), "=r"(r[3]) : "r"(addr));
}
__device__ __forceinline__ void mma16816(float* d, const unsigned* a, const unsigned* b) {
    asm volatile("mma.sync.aligned.m16n8k16.row.col.f32.f16.f16.f32 "
        "{%0,%1,%2,%3}, {%4,%5,%6,%7}, {%8,%9}, {%0,%1,%2,%3};"
        : "+f"(d[0]), "+f"(d[1]), "+f"(d[2]), "+f"(d[3])
        : "r"(a[0]), "r"(a[1]), "r"(a[2]), "r"(a[3]), "r"(b[0]), "r"(b[1]));
}
__device__ __forceinline__ unsigned encf(float f) {
    unsigned u = __float_as_uint(f);
    return (u & 0x80000000u) ? ~u : (u | 0x80000000u);
}
__device__ __forceinline__ float decf(unsigned u) {
    unsigned b = (u & 0x80000000u) ? (u & 0x7FFFFFFFu) : ~u;
    return __uint_as_float(b);
}
__device__ __forceinline__ float quant1(float g, float s, float dm, float sc, float iv,
                                        float cv, float sm) {
    float val = fminf(fmaxf(g - s, -cv), cv);
    float qq  = rintf((val - dm) * sc) * iv + dm;
    return (sm > 0.5f) ? val : qq;
}

// -------------------- prep: split u^T into fp16 hi/mid (scaled), zero accumulators ----
__global__ void prep_k(const float* __restrict__ u) {
    int t = threadIdx.x, b = blockIdx.x;
    if (b < CC) {
        float val = u[(size_t)b*CC + t];          // u[c=b][j=t]
        __half h = __float2half_rn(val);
        __half e = __float2half_rn((val - __half2float(h)) * 2048.0f);
        ut_hi_d[t*CC + b] = h;  ut_mid_d[t*CC + b] = e;   // [j][c] for GEMM1 B
    } else {
        chsum_d[t] = 0.0f; qsum_d[t] = 0.0f;
        gmax_d[t] = 0u; gmin_d[t] = 0xFFFFFFFFu;
    }
}

// -------------------- GEMM --------------------
// MODE 0: g[j][m] = sum_c relu(x[c,m]) * u[c][j]      (3-term split; +chsum, per-j max/min)
// MODE 1: out[c][m] = (sum_j w1024[c][j]*n[j][m])/1024 + bias2[c]   (1-term, n exact fp16)
template<int MODE>
__global__ void __launch_bounds__(NTH)
mgemm_k(const float* __restrict__ X, float* __restrict__ OUT)
{
    extern __shared__ char smem[];
    const uint32_t sb = (uint32_t)__cvta_generic_to_shared(smem);
    const int tid = threadIdx.x;
    const int lane = tid & 31, w = tid >> 5;
    const int m0 = blockIdx.x * 128;
    const int by = blockIdx.y;                 // n-half (0/1)

    float* ps = (float*)smem;                  // param arrays (MODE 1)
    if (MODE) {
        ps[tid]        = s_d[tid];
        ps[256 + tid]  = dmin_d[tid];
        ps[512 + tid]  = scale_d[tid];
        ps[768 + tid]  = cvv_d[tid];
        ps[1024 + tid] = bias_d[tid];
        __syncthreads();
    }

    const int mg = tid & 15, cp = tid >> 4;    // producer coords: 8-m group, k-pair
    const int mrow = m0 + mg*8;
    size_t abase = 0;
    if (!MODE) {
        int nimg = mrow / HWC;
        abase = (size_t)nimg*(CC*HWC) + (size_t)(mrow - nimg*HWC);
    }

    float v[2][8];

    auto loadA = [&](int kc) {
        #pragma unroll
        for (int cc = 0; cc < 2; cc++) {
            int c = kc*32 + cp*2 + cc;
            const float4* p;
            if (!MODE) p = (const float4*)(X + abase + (size_t)c*HWC);
            else       p = (const float4*)(g_buf + (size_t)c*MM + mrow);
            float4 q0 = p[0], q1 = p[1];
            v[cc][0]=q0.x; v[cc][1]=q0.y; v[cc][2]=q0.z; v[cc][3]=q0.w;
            v[cc][4]=q1.x; v[cc][5]=q1.y; v[cc][6]=q1.z; v[cc][7]=q1.w;
        }
    };
    auto procA = [&](int kc, int st) {
        char* base = smem + SO_STG + st*STG_SZ;
        #pragma unroll
        for (int cc = 0; cc < 2; cc++) {
            int c = kc*32 + cp*2 + cc;
            if (!MODE) {
                float s = 0.f;
                #pragma unroll
                for (int i = 0; i < 8; i++) { v[cc][i] = fmaxf(v[cc][i], 0.f); s += v[cc][i]; }
                s += __shfl_xor_sync(~0u, s, 1); s += __shfl_xor_sync(~0u, s, 2);
                s += __shfl_xor_sync(~0u, s, 4); s += __shfl_xor_sync(~0u, s, 8);
                if (by == 0 && (lane & 15) == 0) atomicAdd(&chsum_d[c], s);
            } else {
                float S=ps[c], DM=ps[256+c], SC=ps[512+c], CV=ps[768+c];
                #pragma unroll
                for (int i = 0; i < 8; i++) {
                    float val = fminf(fmaxf(v[cc][i] - S, -CV), CV);
                    v[cc][i] = rintf((val - DM) * SC);   // integer level, exact in fp16
                }
            }
        }
        if (!MODE) {
            #pragma unroll
            for (int i = 0; i < 8; i++) {
                __half h0 = __float2half_rn(v[0][i]);
                __half h1 = __float2half_rn(v[1][i]);
                __half e0 = __float2half_rn((v[0][i] - __half2float(h0)) * 2048.0f);
                __half e1 = __float2half_rn((v[1][i] - __half2float(h1)) * 2048.0f);
                uint32_t off = (uint32_t)(((mg*8 + i)*STRA + cp*2) * 2);
                *(__half2*)(base + STG_AH + off) = __halves2half2(h0, h1);
                *(__half2*)(base + STG_AM + off) = __halves2half2(e0, e1);
            }
        } else {
            #pragma unroll
            for (int i = 0; i < 8; i++) {
                uint32_t off = (uint32_t)(((mg*8 + i)*STRA + cp*2) * 2);
                *(__half2*)(base + STG_AH + off) =
                    __halves2half2(__float2half_rn(v[0][i]), __float2half_rn(v[1][i]));
            }
        }
    };
    auto prodB = [&](int kc, int st) {
        if (!MODE) {
            #pragma unroll
            for (int i = 0; i < 4; i++) {
                int ui = tid + i*NTH;                 // 0..1023
                int ish = (ui < 512);
                int r = (ui & 511) >> 2;              // row 0..127
                int q = ui & 3;
                uint32_t dst = sb + SO_STG + st*STG_SZ + (ish ? STG_BH : STG_BM)
                             + (uint32_t)(r*80 + q*16);
                const __half* s = (ish ? ut_hi_d : ut_mid_d) + (size_t)(by*128 + r)*CC + kc*32 + q*8;
                cp16(dst, s);
            }
        } else {
            // 1-term: only w_hi, 512 16B units
            #pragma unroll
            for (int i = 0; i < 2; i++) {
                int ui = tid + i*NTH;                 // 0..511
                int r = ui >> 2;
                int q = ui & 3;
                uint32_t dst = sb + SO_STG + st*STG_SZ + STG_BH + (uint32_t)(r*80 + q*16);
                cp16(dst, w_hi_d + (size_t)(by*128 + r)*CC + kc*32 + q*8);
            }
        }
    };

    float acch[2][8][4] = {};
    float accm[2][8][4] = {};
    const int wm = (w & 3) * 32;
    const int wn = (w >> 2) * 64;

    prodB(0, 0); cp_commit();
    loadA(0);
    procA(0, 0);

    const int arow = (lane & 15);
    const int asel = (lane >> 4) << 3;
    const int brow = (lane & 7) + ((lane >> 4) << 3);
    const int bsel = ((lane >> 3) & 1) << 3;

    for (int kc = 0; kc < 8; kc++) {
        const int st = kc & 1;
        if (kc < 7) loadA(kc + 1);
        cp_wait0();
        __syncthreads();

        const uint32_t ahb = sb + SO_STG + st*STG_SZ + STG_AH;
        const uint32_t bhb = sb + SO_STG + st*STG_SZ + STG_BH;
        #pragma unroll
        for (int ks = 0; ks < 2; ks++) {
            const int kb = ks*16;
            unsigned ah[2][4], am[2][4];
            #pragma unroll
            for (int mt = 0; mt < 2; mt++) {
                uint32_t ra = ahb + (uint32_t)(((wm + mt*16 + arow)*STRA + kb + asel) * 2);
                ldsm4(ah[mt], ra);
                if (!MODE) ldsm4(am[mt], ra + (STG_AM - STG_AH));
            }
            #pragma unroll
            for (int ng = 0; ng < 4; ng++) {
                uint32_t rb = bhb + (uint32_t)(((wn + ng*16 + brow)*STRA + kb + bsel) * 2);
                unsigned bh[4], bm[4];
                ldsm4(bh, rb);
                if (!MODE) ldsm4(bm, rb + (STG_BM - STG_BH));
                #pragma unroll
                for (int mt = 0; mt < 2; mt++) {
                    if (!MODE) {
                        mma16816(acch[mt][ng*2],     ah[mt], bh);
                        mma16816(acch[mt][ng*2 + 1], ah[mt], bh + 2);
                        mma16816(accm[mt][ng*2],     ah[mt], bm);
                        mma16816(accm[mt][ng*2 + 1], ah[mt], bm + 2);
                        mma16816(accm[mt][ng*2],     am[mt], bh);
                        mma16816(accm[mt][ng*2 + 1], am[mt], bh + 2);
                    } else {
                        mma16816(acch[mt][ng*2],     ah[mt], bh);
                        mma16816(acch[mt][ng*2 + 1], ah[mt], bh + 2);
                    }
                }
            }
        }
        if (kc < 7) { procA(kc + 1, st ^ 1); prodB(kc + 1, st ^ 1); cp_commit(); }
    }
    __syncthreads();   // stage buffers free -> reuse as transpose scratch

    float* scr = (float*)(smem + SO_STG) + w * (64*36);
    #pragma unroll
    for (int mt = 0; mt < 2; mt++)
        #pragma unroll
        for (int nt = 0; nt < 8; nt++)
            #pragma unroll
            for (int i = 0; i < 4; i++) {
                int nl = nt*8 + (lane & 3)*2 + (i & 1);
                int ml = mt*16 + (lane >> 2) + ((i >> 1) << 3);
                scr[nl*36 + ml] = MODE ? acch[mt][nt][i] * INV1024
                                       : acch[mt][nt][i] + accm[mt][nt][i] * INV2048;
            }
    __syncwarp();

    if (!MODE) {
        #pragma unroll 4
        for (int r = 0; r < 64; r++) {
            int j = by*128 + wn + r;
            float val = scr[r*36 + lane];
            float mx = val, mn = val;
            #pragma unroll
            for (int d = 1; d < 32; d <<= 1) {
                mx = fmaxf(mx, __shfl_xor_sync(~0u, mx, d));
                mn = fminf(mn, __shfl_xor_sync(~0u, mn, d));
            }
            g_buf[(size_t)j*MM + m0 + wm + lane] = val;
            if (lane == 0) {
                atomicMax(&gmax_d[j], encf(mx));
                atomicMin(&gmin_d[j], encf(mn));
            }
        }
    } else {
        int mstart = m0 + wm;
        int nimg = mstart / HWC;
        size_t base = (size_t)nimg*(CC*HWC) + (size_t)(mstart - nimg*HWC);
        #pragma unroll 4
        for (int r = 0; r < 64; r++) {
            int c = by*128 + wn + r;
            OUT[base + (size_t)c*HWC + lane] = scr[r*36 + lane] + ps[1024 + c];
        }
    }
}

// -------------------- mid: mn, s, clip, quant params --------------------
__global__ void mid_k(const float* __restrict__ u, const float* __restrict__ cv,
                      const int* __restrict__ abw) {
    __shared__ float mns[CC];
    int t = threadIdx.x;
    float mn = chsum_d[t] * (1.0f / (float)MM);
    mn_d[t] = mn; mns[t] = mn;
    __syncthreads();
    float s = 0.0f;
    #pragma unroll 8
    for (int c = 0; c < CC; c++) s += u[(size_t)c*CC + t] * mns[c];
    s_d[t] = s;
    float c = cv[t]; cvv_d[t] = c;
    int ab = abw ? *abw : 8;
    float dmax = fminf(fmaxf(decf(gmax_d[t]) - s, -c), c);
    float dmin = fminf(fmaxf(decf(gmin_d[t]) - s, -c), c);
    int same = (dmax == dmin) || (ab >= 17);
    float rng = same ? 1.0f : (dmax - dmin);
    float levels = (float)((1 << (same ? 8 : ab)) - 1);
    same_d[t]  = same ? 1.0f : 0.0f;
    dmin_d[t]  = dmin;
    scale_d[t] = levels / rng;
    inv_d[t]   = rng / levels;
}

// -------------------- wsplit: w1024 = fp16(u*iv*1024) --------------------
__global__ void wsplit_k(const float* __restrict__ u) {
    int c = blockIdx.x, j = threadIdx.x;
    float wv = u[(size_t)c*CC + j] * inv_d[j] * 1024.0f;
    w_hi_d[c*CC + j] = __float2half_rn(wv);
}

// -------------------- qsum: MLP-4 quant reduction --------------------
__global__ void __launch_bounds__(128) qsum_k() {
    __shared__ float red[4];
    int j = blockIdx.y;
    float s = s_d[j], dm = dmin_d[j], sc = scale_d[j], iv = inv_d[j],
          cv = cvv_d[j], smf = same_d[j];
    size_t base = (size_t)j*MM + (size_t)blockIdx.x*2048 + threadIdx.x*4;
    float4 v0 = *(const float4*)(g_buf + base);
    float4 v1 = *(const float4*)(g_buf + base + 512);
    float4 v2 = *(const float4*)(g_buf + base + 1024);
    float4 v3 = *(const float4*)(g_buf + base + 1536);
    float sum = quant1(v0.x,s,dm,sc,iv,cv,smf) + quant1(v0.y,s,dm,sc,iv,cv,smf)
              + quant1(v0.z,s,dm,sc,iv,cv,smf) + quant1(v0.w,s,dm,sc,iv,cv,smf)
              + quant1(v1.x,s,dm,sc,iv,cv,smf) + quant1(v1.y,s,dm,sc,iv,cv,smf)
              + quant1(v1.z,s,dm,sc,iv,cv,smf) + quant1(v1.w,s,dm,sc,iv,cv,smf)
              + quant1(v2.x,s,dm,sc,iv,cv,smf) + quant1(v2.y,s,dm,sc,iv,cv,smf)
              + quant1(v2.z,s,dm,sc,iv,cv,smf) + quant1(v2.w,s,dm,sc,iv,cv,smf)
              + quant1(v3.x,s,dm,sc,iv,cv,smf) + quant1(v3.y,s,dm,sc,iv,cv,smf)
              + quant1(v3.z,s,dm,sc,iv,cv,smf) + quant1(v3.w,s,dm,sc,iv,cv,smf);
    #pragma unroll
    for (int d = 1; d < 32; d <<= 1) sum += __shfl_xor_sync(~0u, sum, d);
    int lane = threadIdx.x & 31, wid = threadIdx.x >> 5;
    if (lane == 0) red[wid] = sum;
    __syncthreads();
    if (threadIdx.x == 0)
        atomicAdd(&qsum_d[j], red[0] + red[1] + red[2] + red[3]);
}

// -------------------- bias2[c] = mn[c] + sum_j u[c][j]*(dmin[j] - qmean[j]) ----
__global__ void bias_k(const float* __restrict__ u) {
    __shared__ float dq[CC];
    int t = threadIdx.x;
    dq[t] = dmin_d[t] - qsum_d[t] * (1.0f / (float)MM);
    __syncthreads();
    float b = 0.0f;
    #pragma unroll 8
    for (int j = 0; j < CC; j++) b += u[(size_t)t*CC + j] * dq[j];
    bias_d[t] = mn_d[t] + b;
}

// -------------------- launcher --------------------
extern "C" void kernel_launch(void* const* d_in, const int* in_sizes, int n_in,
                              void* d_out, int out_size) {
    const float* x  = (const float*)d_in[0];
    const float* u  = (const float*)d_in[1];
    const float* cv = (const float*)d_in[2];
    const int*   ab = (n_in > 3) ? (const int*)d_in[3] : nullptr;
    float* out = (float*)d_out;
    (void)in_sizes; (void)out_size;

    cudaFuncSetAttribute(mgemm_k<0>, cudaFuncAttributeMaxDynamicSharedMemorySize, SMEM_T);
    cudaFuncSetAttribute(mgemm_k<1>, cudaFuncAttributeMaxDynamicSharedMemorySize, SMEM_T);

    prep_k<<<CC + 1, CC>>>(u);
    mgemm_k<0><<<dim3(NTILE, 2), NTH, SMEM_T>>>(x, nullptr);
    mid_k<<<1, CC>>>(u, cv, ab);
    wsplit_k<<<CC, CC>>>(u);
    qsum_k<<<dim3(49, CC), 128>>>();
    bias_k<<<1, CC>>>(u);
    mgemm_k<1><<<dim3(NTILE, 2), NTH, SMEM_T>>>(nullptr, out);
}

// round 12
// speedup vs baseline: 1.3247x; 1.0167x over previous
#include <cuda_runtime.h>
#include <cuda_fp16.h>
#include <cstdint>

#define CC 256
#define HWC 3136
#define MM 100352
#define NTILE 784
#define NTH 256
#define STRA 40                 /* halfs per smem row (80B, conflict-free ldmatrix) */
#define STG_AH 0
#define STG_AM 10240
#define STG_BH 20480
#define STG_BM 30720
#define STG_SZ 40960
#define SO_STG 8192
#define SMEM_T (SO_STG + 2*STG_SZ)   /* 90112 */
#define INV2048 (1.0f/2048.0f)
#define INV1024 (1.0f/1024.0f)

// -------------------- device scratch --------------------
__device__ __align__(16) float  g_buf[(size_t)CC*MM];
__device__ __align__(16) __half ut_hi_d[CC*CC], ut_mid_d[CC*CC];   // GEMM1 B [j][c]
__device__ __align__(16) __half w_hi_d[CC*CC];                     // GEMM2 B [c][j] = fp16(u*iv*1024)
__device__ float    chsum_d[CC];
__device__ unsigned gmax_d[CC], gmin_d[CC];
__device__ float    mn_d[CC], s_d[CC], dmin_d[CC], scale_d[CC], inv_d[CC], cvv_d[CC];
__device__ float    qsum_d[CC], bias_d[CC], same_d[CC];

// -------------------- helpers --------------------
__device__ __forceinline__ void cp16(uint32_t sdst, const void* g) {
    asm volatile("cp.async.ca.shared.global [%0], [%1], 16;" :: "r"(sdst), "l"(g) : "memory");
}
__device__ __forceinline__ void cp_commit() { asm volatile("cp.async.commit_group;" ::: "memory"); }
__device__ __forceinline__ void cp_wait0()  { asm volatile("cp.async.wait_group 0;" ::: "memory"); }

__device__ __forceinline__ void ldsm4(unsigned* r, uint32_t addr) {
    asm volatile("ldmatrix.sync.aligned.m8n8.x4.shared.b16 {%0,%1,%2,%3}, [%4];"
        : "=r"(r[0]), "=r"(r[1]), "=r"(r[2]), "=r"(r[3]) : "r"(addr));
}
__device__ __forceinline__ void mma16816(float* d, const unsigned* a, const unsigned* b) {
    asm volatile("mma.sync.aligned.m16n8k16.row.col.f32.f16.f16.f32 "
        "{%0,%1,%2,%3}, {%4,%5,%6,%7}, {%8,%9}, {%0,%1,%2,%3};"
        : "+f"(d[0]), "+f"(d[1]), "+f"(d[2]), "+f"(d[3])
        : "r"(a[0]), "r"(a[1]), "r"(a[2]), "r"(a[3]), "r"(b[0]), "r"(b[1]));
}
__device__ __forceinline__ unsigned encf(float f) {
    unsigned u = __float_as_uint(f);
    return (u & 0x80000000u) ? ~u : (u | 0x80000000u);
}
__device__ __forceinline__ float decf(unsigned u) {
    unsigned b = (u & 0x80000000u) ? (u & 0x7FFFFFFFu) : ~u;
    return __uint_as_float(b);
}
// folded quantizer used identically by qsum_k and GEMM2 producer:
// n = rint(clamp(g*sc + negC, lo, hi)),  q = n*iv + dm
__device__ __forceinline__ float qlevel(float g, float sc, float negC, float lo, float hi) {
    return rintf(fminf(fmaxf(fmaf(g, sc, negC), lo), hi));
}

// -------------------- prep: split u^T into fp16 hi/mid (scaled), zero accumulators ----
__global__ void prep_k(const float* __restrict__ u) {
    int t = threadIdx.x, b = blockIdx.x;
    if (b < CC) {
        float val = u[(size_t)b*CC + t];          // u[c=b][j=t]
        __half h = __float2half_rn(val);
        __half e = __float2half_rn((val - __half2float(h)) * 2048.0f);
        ut_hi_d[t*CC + b] = h;  ut_mid_d[t*CC + b] = e;   // [j][c] for GEMM1 B
    } else {
        chsum_d[t] = 0.0f; qsum_d[t] = 0.0f;
        gmax_d[t] = 0u; gmin_d[t] = 0xFFFFFFFFu;
    }
}

// -------------------- GEMM --------------------
// MODE 0: g[j][m] = sum_c relu(x[c,m]) * u[c][j]      (3-term split; +chsum, per-j max/min)
// MODE 1: out[c][m] = (sum_j w1024[c][j]*n[j][m])/1024 + bias2[c]   (1-term, n exact fp16)
// Producer phase (procA/prodB for kc+1) hoisted ABOVE the MMA block so cp.async/STS
// latency is covered by the MMA block instead of being exposed at the next cp_wait0.
template<int MODE>
__global__ void __launch_bounds__(NTH)
mgemm_k(const float* __restrict__ X, float* __restrict__ OUT)
{
    extern __shared__ char smem[];
    const uint32_t sb = (uint32_t)__cvta_generic_to_shared(smem);
    const int tid = threadIdx.x;
    const int lane = tid & 31, w = tid >> 5;
    const int m0 = blockIdx.x * 128;
    const int by = blockIdx.y;                 // n-half (0/1)

    float* ps = (float*)smem;                  // param arrays (MODE 1)
    if (MODE) {
        // folded quant params: negC, lo, hi, sc + bias
        float s  = s_d[tid], dm = dmin_d[tid], sc = scale_d[tid], cv = cvv_d[tid];
        ps[tid]        = -(s + dm) * sc;       // negC
        ps[256 + tid]  = (-cv - dm) * sc;      // lo
        ps[512 + tid]  = sc;
        ps[768 + tid]  = (cv - dm) * sc;       // hi
        ps[1024 + tid] = bias_d[tid];
        __syncthreads();
    }

    const int mg = tid & 15, cp = tid >> 4;    // producer coords: 8-m group, k-pair
    const int mrow = m0 + mg*8;
    size_t abase = 0;
    if (!MODE) {
        int nimg = mrow / HWC;
        abase = (size_t)nimg*(CC*HWC) + (size_t)(mrow - nimg*HWC);
    }

    float v[2][8];

    auto loadA = [&](int kc) {
        #pragma unroll
        for (int cc = 0; cc < 2; cc++) {
            int c = kc*32 + cp*2 + cc;
            const float4* p;
            if (!MODE) p = (const float4*)(X + abase + (size_t)c*HWC);
            else       p = (const float4*)(g_buf + (size_t)c*MM + mrow);
            float4 q0 = p[0], q1 = p[1];
            v[cc][0]=q0.x; v[cc][1]=q0.y; v[cc][2]=q0.z; v[cc][3]=q0.w;
            v[cc][4]=q1.x; v[cc][5]=q1.y; v[cc][6]=q1.z; v[cc][7]=q1.w;
        }
    };
    auto procA = [&](int kc, int st) {
        char* base = smem + SO_STG + st*STG_SZ;
        #pragma unroll
        for (int cc = 0; cc < 2; cc++) {
            int c = kc*32 + cp*2 + cc;
            if (!MODE) {
                float s = 0.f;
                #pragma unroll
                for (int i = 0; i < 8; i++) { v[cc][i] = fmaxf(v[cc][i], 0.f); s += v[cc][i]; }
                s += __shfl_xor_sync(~0u, s, 1); s += __shfl_xor_sync(~0u, s, 2);
                s += __shfl_xor_sync(~0u, s, 4); s += __shfl_xor_sync(~0u, s, 8);
                if (by == 0 && (lane & 15) == 0) atomicAdd(&chsum_d[c], s);
            } else {
                float NC=ps[c], LO=ps[256+c], SC=ps[512+c], HI=ps[768+c];
                #pragma unroll
                for (int i = 0; i < 8; i++)
                    v[cc][i] = qlevel(v[cc][i], SC, NC, LO, HI);   // integer level, exact fp16
            }
        }
        if (!MODE) {
            #pragma unroll
            for (int i = 0; i < 8; i++) {
                __half h0 = __float2half_rn(v[0][i]);
                __half h1 = __float2half_rn(v[1][i]);
                __half e0 = __float2half_rn((v[0][i] - __half2float(h0)) * 2048.0f);
                __half e1 = __float2half_rn((v[1][i] - __half2float(h1)) * 2048.0f);
                uint32_t off = (uint32_t)(((mg*8 + i)*STRA + cp*2) * 2);
                *(__half2*)(base + STG_AH + off) = __halves2half2(h0, h1);
                *(__half2*)(base + STG_AM + off) = __halves2half2(e0, e1);
            }
        } else {
            #pragma unroll
            for (int i = 0; i < 8; i++) {
                uint32_t off = (uint32_t)(((mg*8 + i)*STRA + cp*2) * 2);
                *(__half2*)(base + STG_AH + off) =
                    __halves2half2(__float2half_rn(v[0][i]), __float2half_rn(v[1][i]));
            }
        }
    };
    auto prodB = [&](int kc, int st) {
        if (!MODE) {
            #pragma unroll
            for (int i = 0; i < 4; i++) {
                int ui = tid + i*NTH;                 // 0..1023
                int ish = (ui < 512);
                int r = (ui & 511) >> 2;              // row 0..127
                int q = ui & 3;
                uint32_t dst = sb + SO_STG + st*STG_SZ + (ish ? STG_BH : STG_BM)
                             + (uint32_t)(r*80 + q*16);
                const __half* s = (ish ? ut_hi_d : ut_mid_d) + (size_t)(by*128 + r)*CC + kc*32 + q*8;
                cp16(dst, s);
            }
        } else {
            // 1-term: only w_hi, 512 16B units
            #pragma unroll
            for (int i = 0; i < 2; i++) {
                int ui = tid + i*NTH;                 // 0..511
                int r = ui >> 2;
                int q = ui & 3;
                uint32_t dst = sb + SO_STG + st*STG_SZ + STG_BH + (uint32_t)(r*80 + q*16);
                cp16(dst, w_hi_d + (size_t)(by*128 + r)*CC + kc*32 + q*8);
            }
        }
    };

    float acch[2][8][4] = {};
    float accm[2][8][4] = {};
    const int wm = (w & 3) * 32;
    const int wn = (w >> 2) * 64;

    // prologue: fill stage 0, prefetch A chunk 1
    loadA(0);
    procA(0, 0);
    prodB(0, 0); cp_commit();
    loadA(1);

    const int arow = (lane & 15);
    const int asel = (lane >> 4) << 3;
    const int brow = (lane & 7) + ((lane >> 4) << 3);
    const int bsel = ((lane >> 3) & 1) << 3;

    for (int kc = 0; kc < 8; kc++) {
        const int st = kc & 1;
        cp_wait0();
        __syncthreads();            // st ready; also: all reads of st^1 (from kc-1) done

        // producer phase for kc+1 -> st^1 (covered by the MMA block below)
        if (kc < 7) { procA(kc + 1, st ^ 1); prodB(kc + 1, st ^ 1); cp_commit(); }
        if (kc < 6) loadA(kc + 2);

        const uint32_t ahb = sb + SO_STG + st*STG_SZ + STG_AH;
        const uint32_t bhb = sb + SO_STG + st*STG_SZ + STG_BH;
        #pragma unroll
        for (int ks = 0; ks < 2; ks++) {
            const int kb = ks*16;
            unsigned ah[2][4], am[2][4];
            #pragma unroll
            for (int mt = 0; mt < 2; mt++) {
                uint32_t ra = ahb + (uint32_t)(((wm + mt*16 + arow)*STRA + kb + asel) * 2);
                ldsm4(ah[mt], ra);
                if (!MODE) ldsm4(am[mt], ra + (STG_AM - STG_AH));
            }
            #pragma unroll
            for (int ng = 0; ng < 4; ng++) {
                uint32_t rb = bhb + (uint32_t)(((wn + ng*16 + brow)*STRA + kb + bsel) * 2);
                unsigned bh[4], bm[4];
                ldsm4(bh, rb);
                if (!MODE) ldsm4(bm, rb + (STG_BM - STG_BH));
                #pragma unroll
                for (int mt = 0; mt < 2; mt++) {
                    if (!MODE) {
                        mma16816(acch[mt][ng*2],     ah[mt], bh);
                        mma16816(acch[mt][ng*2 + 1], ah[mt], bh + 2);
                        mma16816(accm[mt][ng*2],     ah[mt], bm);
                        mma16816(accm[mt][ng*2 + 1], ah[mt], bm + 2);
                        mma16816(accm[mt][ng*2],     am[mt], bh);
                        mma16816(accm[mt][ng*2 + 1], am[mt], bh + 2);
                    } else {
                        mma16816(acch[mt][ng*2],     ah[mt], bh);
                        mma16816(acch[mt][ng*2 + 1], ah[mt], bh + 2);
                    }
                }
            }
        }
    }
    __syncthreads();   // stage buffers free -> reuse as transpose scratch

    float* scr = (float*)(smem + SO_STG) + w * (64*36);
    #pragma unroll
    for (int mt = 0; mt < 2; mt++)
        #pragma unroll
        for (int nt = 0; nt < 8; nt++)
            #pragma unroll
            for (int i = 0; i < 4; i++) {
                int nl = nt*8 + (lane & 3)*2 + (i & 1);
                int ml = mt*16 + (lane >> 2) + ((i >> 1) << 3);
                scr[nl*36 + ml] = MODE ? acch[mt][nt][i] * INV1024
                                       : acch[mt][nt][i] + accm[mt][nt][i] * INV2048;
            }
    __syncwarp();

    if (!MODE) {
        #pragma unroll 4
        for (int r = 0; r < 64; r++) {
            int j = by*128 + wn + r;
            float val = scr[r*36 + lane];
            float mx = val, mn = val;
            #pragma unroll
            for (int d = 1; d < 32; d <<= 1) {
                mx = fmaxf(mx, __shfl_xor_sync(~0u, mx, d));
                mn = fminf(mn, __shfl_xor_sync(~0u, mn, d));
            }
            g_buf[(size_t)j*MM + m0 + wm + lane] = val;
            if (lane == 0) {
                atomicMax(&gmax_d[j], encf(mx));
                atomicMin(&gmin_d[j], encf(mn));
            }
        }
    } else {
        int mstart = m0 + wm;
        int nimg = mstart / HWC;
        size_t base = (size_t)nimg*(CC*HWC) + (size_t)(mstart - nimg*HWC);
        #pragma unroll 4
        for (int r = 0; r < 64; r++) {
            int c = by*128 + wn + r;
            OUT[base + (size_t)c*HWC + lane] = scr[r*36 + lane] + ps[1024 + c];
        }
    }
}

// -------------------- mid: mn, s, clip, quant params --------------------
__global__ void mid_k(const float* __restrict__ u, const float* __restrict__ cv,
                      const int* __restrict__ abw) {
    __shared__ float mns[CC];
    int t = threadIdx.x;
    float mn = chsum_d[t] * (1.0f / (float)MM);
    mn_d[t] = mn; mns[t] = mn;
    __syncthreads();
    float s = 0.0f;
    #pragma unroll 8
    for (int c = 0; c < CC; c++) s += u[(size_t)c*CC + t] * mns[c];
    s_d[t] = s;
    float c = cv[t]; cvv_d[t] = c;
    int ab = abw ? *abw : 8;
    float dmax = fminf(fmaxf(decf(gmax_d[t]) - s, -c), c);
    float dmin = fminf(fmaxf(decf(gmin_d[t]) - s, -c), c);
    int same = (dmax == dmin) || (ab >= 17);
    float rng = same ? 1.0f : (dmax - dmin);
    float levels = (float)((1 << (same ? 8 : ab)) - 1);
    same_d[t]  = same ? 1.0f : 0.0f;
    dmin_d[t]  = dmin;
    scale_d[t] = levels / rng;
    inv_d[t]   = rng / levels;
}

// -------------------- wsplit: w1024 = fp16(u*iv*1024) --------------------
__global__ void wsplit_k(const float* __restrict__ u) {
    int c = blockIdx.x, j = threadIdx.x;
    float wv = u[(size_t)c*CC + j] * inv_d[j] * 1024.0f;
    w_hi_d[c*CC + j] = __float2half_rn(wv);
}

// -------------------- qsum: MLP-4 quant reduction (folded form, matches GEMM2) ----
__global__ void __launch_bounds__(128) qsum_k() {
    __shared__ float red[4];
    int j = blockIdx.y;
    float s = s_d[j], dm = dmin_d[j], sc = scale_d[j], iv = inv_d[j],
          cv = cvv_d[j], smf = same_d[j];
    float NC = -(s + dm) * sc;
    float LO = (-cv - dm) * sc;
    float HI = (cv - dm) * sc;
    size_t base = (size_t)j*MM + (size_t)blockIdx.x*2048 + threadIdx.x*4;
    float4 v0 = *(const float4*)(g_buf + base);
    float4 v1 = *(const float4*)(g_buf + base + 512);
    float4 v2 = *(const float4*)(g_buf + base + 1024);
    float4 v3 = *(const float4*)(g_buf + base + 1536);
    float gg[16] = { v0.x,v0.y,v0.z,v0.w, v1.x,v1.y,v1.z,v1.w,
                     v2.x,v2.y,v2.z,v2.w, v3.x,v3.y,v3.z,v3.w };
    float sum = 0.f;
    #pragma unroll
    for (int i = 0; i < 16; i++) {
        float q;
        if (smf > 0.5f) q = fminf(fmaxf(gg[i] - s, -cv), cv);       // same: unquantized val
        else            q = fmaf(qlevel(gg[i], sc, NC, LO, HI), iv, dm);
        sum += q;
    }
    #pragma unroll
    for (int d = 1; d < 32; d <<= 1) sum += __shfl_xor_sync(~0u, sum, d);
    int lane = threadIdx.x & 31, wid = threadIdx.x >> 5;
    if (lane == 0) red[wid] = sum;
    __syncthreads();
    if (threadIdx.x == 0)
        atomicAdd(&qsum_d[j], red[0] + red[1] + red[2] + red[3]);
}

// -------------------- bias2[c] = mn[c] + sum_j u[c][j]*(dmin[j] - qmean[j]) ----
__global__ void bias_k(const float* __restrict__ u) {
    __shared__ float dq[CC];
    int t = threadIdx.x;
    dq[t] = dmin_d[t] - qsum_d[t] * (1.0f / (float)MM);
    __syncthreads();
    float b = 0.0f;
    #pragma unroll 8
    for (int j = 0; j < CC; j++) b += u[(size_t)t*CC + j] * dq[j];
    bias_d[t] = mn_d[t] + b;
}

// -------------------- launcher --------------------
extern "C" void kernel_launch(void* const* d_in, const int* in_sizes, int n_in,
                              void* d_out, int out_size) {
    const float* x  = (const float*)d_in[0];
    const float* u  = (const float*)d_in[1];
    const float* cv = (const float*)d_in[2];
    const int*   ab = (n_in > 3) ? (const int*)d_in[3] : nullptr;
    float* out = (float*)d_out;
    (void)in_sizes; (void)out_size;

    cudaFuncSetAttribute(mgemm_k<0>, cudaFuncAttributeMaxDynamicSharedMemorySize, SMEM_T);
    cudaFuncSetAttribute(mgemm_k<1>, cudaFuncAttributeMaxDynamicSharedMemorySize, SMEM_T);

    prep_k<<<CC + 1, CC>>>(u);
    mgemm_k<0><<<dim3(NTILE, 2), NTH, SMEM_T>>>(x, nullptr);
    mid_k<<<1, CC>>>(u, cv, ab);
    wsplit_k<<<CC, CC>>>(u);
    qsum_k<<<dim3(49, CC), 128>>>();
    bias_k<<<1, CC>>>(u);
    mgemm_k<1><<<dim3(NTILE, 2), NTH, SMEM_T>>>(nullptr, out);
}

// round 13
// speedup vs baseline: 1.3596x; 1.0263x over previous
#include <cuda_runtime.h>
#include <cuda_fp16.h>
#include <cstdint>

#define CC 256
#define HWC 3136
#define MM 100352
#define NTILE 784
#define NTH 256
#define STRA 40                 /* halfs per smem row (80B, conflict-free ldmatrix) */
/* MODE0 stage: AH 10240 | AM 10240 | BH 10240 | BM 10240  (40960) */
#define STG_AH 0
#define STG_AM 10240
#define STG_BH 20480
#define STG_BM 30720
#define STG_SZ0 40960
/* MODE1 stage: AH 10240 | B 20480 (256 rows)  (30720) */
#define STG_B1 10240
#define STG_SZ1 30720
#define SO_STG 8192
#define SMEM_T (SO_STG + 2*STG_SZ0)   /* 90112 */
#define INV2048 (1.0f/2048.0f)
#define INV1024 (1.0f/1024.0f)

// -------------------- device scratch --------------------
__device__ __align__(16) float  g_buf[(size_t)CC*MM];
__device__ __align__(16) __half ut_hi_d[CC*CC], ut_mid_d[CC*CC];   // GEMM1 B [j][c]
__device__ __align__(16) __half w_hi_d[CC*CC];                     // GEMM2 B [c][j] = fp16(u*iv*1024)
__device__ float    chsum_d[CC];
__device__ unsigned gmax_d[CC], gmin_d[CC];
__device__ float    mn_d[CC], s_d[CC], dmin_d[CC], scale_d[CC], inv_d[CC], cvv_d[CC];
__device__ float    qsum_d[CC], bias_d[CC], same_d[CC];

// -------------------- helpers --------------------
__device__ __forceinline__ void cp16(uint32_t sdst, const void* g) {
    asm volatile("cp.async.ca.shared.global [%0], [%1], 16;" :: "r"(sdst), "l"(g) : "memory");
}
__device__ __forceinline__ void cp_commit() { asm volatile("cp.async.commit_group;" ::: "memory"); }
__device__ __forceinline__ void cp_wait0()  { asm volatile("cp.async.wait_group 0;" ::: "memory"); }

__device__ __forceinline__ void ldsm4(unsigned* r, uint32_t addr) {
    asm volatile("ldmatrix.sync.aligned.m8n8.x4.shared.b16 {%0,%1,%2,%3}, [%4];"
        : "=r"(r[0]), "=r"(r[1]), "=r"(r[2]), "=r"(r[3]) : "r"(addr));
}
__device__ __forceinline__ void mma16816(float* d, const unsigned* a, const unsigned* b) {
    asm volatile("mma.sync.aligned.m16n8k16.row.col.f32.f16.f16.f32 "
        "{%0,%1,%2,%3}, {%4,%5,%6,%7}, {%8,%9}, {%0,%1,%2,%3};"
        : "+f"(d[0]), "+f"(d[1]), "+f"(d[2]), "+f"(d[3])
        : "r"(a[0]), "r"(a[1]), "r"(a[2]), "r"(a[3]), "r"(b[0]), "r"(b[1]));
}
__device__ __forceinline__ unsigned encf(float f) {
    unsigned u = __float_as_uint(f);
    return (u & 0x80000000u) ? ~u : (u | 0x80000000u);
}
__device__ __forceinline__ float decf(unsigned u) {
    unsigned b = (u & 0x80000000u) ? (u & 0x7FFFFFFFu) : ~u;
    return __uint_as_float(b);
}
// folded quantizer (identical in qsum_k and GEMM2 producer):
// n = rint(clamp(g*sc + negC, lo, hi)),  q = n*iv + dm
__device__ __forceinline__ float qlevel(float g, float sc, float negC, float lo, float hi) {
    return rintf(fminf(fmaxf(fmaf(g, sc, negC), lo), hi));
}

// -------------------- prep --------------------
__global__ void prep_k(const float* __restrict__ u) {
    int t = threadIdx.x, b = blockIdx.x;
    if (b < CC) {
        float val = u[(size_t)b*CC + t];          // u[c=b][j=t]
        __half h = __float2half_rn(val);
        __half e = __float2half_rn((val - __half2float(h)) * 2048.0f);
        ut_hi_d[t*CC + b] = h;  ut_mid_d[t*CC + b] = e;   // [j][c] for GEMM1 B
    } else {
        chsum_d[t] = 0.0f; qsum_d[t] = 0.0f;
        gmax_d[t] = 0u; gmin_d[t] = 0xFFFFFFFFu;
    }
}

// -------------------- GEMM --------------------
// MODE 0: g[j][m] = sum_c relu(x[c,m]) * u[c][j]   grid (2, NTILE): x=n-half, y=m-tile
//         (adjacent bids share x tiles -> L2 dedup)
// MODE 1: out[c][m] = (sum_j w1024[c][j]*n[j][m])/1024 + bias2[c]   grid (NTILE, 1)
//         full N=256 per CTA (1-term fp16, n exact) — g_buf read ONCE.
template<int MODE>
__global__ void __launch_bounds__(NTH)
mgemm_k(const float* __restrict__ X, float* __restrict__ OUT)
{
    extern __shared__ char smem[];
    const uint32_t sb = (uint32_t)__cvta_generic_to_shared(smem);
    const int tid = threadIdx.x;
    const int lane = tid & 31, w = tid >> 5;
    const int m0 = (MODE ? blockIdx.x : blockIdx.y) * 128;
    const int by = MODE ? 0 : blockIdx.x;       // n-half (MODE0 only)
    const int STGSZ = MODE ? STG_SZ1 : STG_SZ0;

    float* ps = (float*)smem;                   // param arrays (MODE 1)
    if (MODE) {
        float s  = s_d[tid], dm = dmin_d[tid], sc = scale_d[tid], cv = cvv_d[tid];
        ps[tid]        = -(s + dm) * sc;        // negC
        ps[256 + tid]  = (-cv - dm) * sc;       // lo
        ps[512 + tid]  = sc;
        ps[768 + tid]  = (cv - dm) * sc;        // hi
        ps[1024 + tid] = bias_d[tid];
        __syncthreads();
    }

    const int mg = tid & 15, cp = tid >> 4;     // producer coords: 8-m group, k-pair
    const int mrow = m0 + mg*8;
    size_t abase = 0;
    if (!MODE) {
        int nimg = mrow / HWC;
        abase = (size_t)nimg*(CC*HWC) + (size_t)(mrow - nimg*HWC);
    }

    float v[2][8];

    auto loadA = [&](int kc) {
        #pragma unroll
        for (int cc = 0; cc < 2; cc++) {
            int c = kc*32 + cp*2 + cc;
            const float4* p;
            if (!MODE) p = (const float4*)(X + abase + (size_t)c*HWC);
            else       p = (const float4*)(g_buf + (size_t)c*MM + mrow);
            float4 q0 = p[0], q1 = p[1];
            v[cc][0]=q0.x; v[cc][1]=q0.y; v[cc][2]=q0.z; v[cc][3]=q0.w;
            v[cc][4]=q1.x; v[cc][5]=q1.y; v[cc][6]=q1.z; v[cc][7]=q1.w;
        }
    };
    auto procA = [&](int kc, int st) {
        char* base = smem + SO_STG + st*STGSZ;
        #pragma unroll
        for (int cc = 0; cc < 2; cc++) {
            int c = kc*32 + cp*2 + cc;
            if (!MODE) {
                float s = 0.f;
                #pragma unroll
                for (int i = 0; i < 8; i++) { v[cc][i] = fmaxf(v[cc][i], 0.f); s += v[cc][i]; }
                s += __shfl_xor_sync(~0u, s, 1); s += __shfl_xor_sync(~0u, s, 2);
                s += __shfl_xor_sync(~0u, s, 4); s += __shfl_xor_sync(~0u, s, 8);
                if (by == 0 && (lane & 15) == 0) atomicAdd(&chsum_d[c], s);
            } else {
                float NC=ps[c], LO=ps[256+c], SC=ps[512+c], HI=ps[768+c];
                #pragma unroll
                for (int i = 0; i < 8; i++)
                    v[cc][i] = qlevel(v[cc][i], SC, NC, LO, HI);   // exact fp16 integer
            }
        }
        if (!MODE) {
            #pragma unroll
            for (int i = 0; i < 8; i++) {
                __half h0 = __float2half_rn(v[0][i]);
                __half h1 = __float2half_rn(v[1][i]);
                __half e0 = __float2half_rn((v[0][i] - __half2float(h0)) * 2048.0f);
                __half e1 = __float2half_rn((v[1][i] - __half2float(h1)) * 2048.0f);
                uint32_t off = (uint32_t)(((mg*8 + i)*STRA + cp*2) * 2);
                *(__half2*)(base + STG_AH + off) = __halves2half2(h0, h1);
                *(__half2*)(base + STG_AM + off) = __halves2half2(e0, e1);
            }
        } else {
            #pragma unroll
            for (int i = 0; i < 8; i++) {
                uint32_t off = (uint32_t)(((mg*8 + i)*STRA + cp*2) * 2);
                *(__half2*)(base + STG_AH + off) =
                    __halves2half2(__float2half_rn(v[0][i]), __float2half_rn(v[1][i]));
            }
        }
    };
    auto prodB = [&](int kc, int st) {
        if (!MODE) {
            #pragma unroll
            for (int i = 0; i < 4; i++) {
                int ui = tid + i*NTH;                 // 0..1023
                int ish = (ui < 512);
                int r = (ui & 511) >> 2;              // row 0..127
                int q = ui & 3;
                uint32_t dst = sb + SO_STG + st*STGSZ + (ish ? STG_BH : STG_BM)
                             + (uint32_t)(r*80 + q*16);
                const __half* s = (ish ? ut_hi_d : ut_mid_d) + (size_t)(by*128 + r)*CC + kc*32 + q*8;
                cp16(dst, s);
            }
        } else {
            // full N: 256 rows x 4 units = 1024 16B units
            #pragma unroll
            for (int i = 0; i < 4; i++) {
                int ui = tid + i*NTH;                 // 0..1023
                int r = ui >> 2;                      // row 0..255
                int q = ui & 3;
                uint32_t dst = sb + SO_STG + st*STGSZ + STG_B1 + (uint32_t)(r*80 + q*16);
                cp16(dst, w_hi_d + (size_t)r*CC + kc*32 + q*8);
            }
        }
    };

    // acc: MODE0 = acch+accm[2][8][4] (n-tile 64); MODE1 = acch[2][16][4] (n-tile 128)
    float acch[2][MODE ? 16 : 8][4] = {};
    float accm[2][MODE ? 1 : 8][4] = {};
    const int wm = (w & 3) * 32;
    const int wn = (w >> 2) * (MODE ? 128 : 64);
    const int NG = MODE ? 8 : 4;

    // prologue: fill stage 0, prefetch A chunk 1
    loadA(0);
    procA(0, 0);
    prodB(0, 0); cp_commit();
    loadA(1);

    const int arow = (lane & 15);
    const int asel = (lane >> 4) << 3;
    const int brow = (lane & 7) + ((lane >> 4) << 3);
    const int bsel = ((lane >> 3) & 1) << 3;

    for (int kc = 0; kc < 8; kc++) {
        const int st = kc & 1;
        cp_wait0();
        __syncthreads();            // st ready; reads of st^1 (kc-1) complete

        if (kc < 7) { procA(kc + 1, st ^ 1); prodB(kc + 1, st ^ 1); cp_commit(); }
        if (kc < 6) loadA(kc + 2);

        const uint32_t ahb = sb + SO_STG + st*STGSZ + STG_AH;
        const uint32_t bhb = sb + SO_STG + st*STGSZ + (MODE ? STG_B1 : STG_BH);
        #pragma unroll
        for (int ks = 0; ks < 2; ks++) {
            const int kb = ks*16;
            unsigned ah[2][4], am[2][4];
            #pragma unroll
            for (int mt = 0; mt < 2; mt++) {
                uint32_t ra = ahb + (uint32_t)(((wm + mt*16 + arow)*STRA + kb + asel) * 2);
                ldsm4(ah[mt], ra);
                if (!MODE) ldsm4(am[mt], ra + (STG_AM - STG_AH));
            }
            #pragma unroll
            for (int ng = 0; ng < NG; ng++) {
                uint32_t rb = bhb + (uint32_t)(((wn + ng*16 + brow)*STRA + kb + bsel) * 2);
                unsigned bh[4], bm[4];
                ldsm4(bh, rb);
                if (!MODE) ldsm4(bm, rb + (STG_BM - STG_BH));
                #pragma unroll
                for (int mt = 0; mt < 2; mt++) {
                    if (!MODE) {
                        mma16816(acch[mt][ng*2],     ah[mt], bh);
                        mma16816(acch[mt][ng*2 + 1], ah[mt], bh + 2);
                        mma16816(accm[mt][ng*2],     ah[mt], bm);
                        mma16816(accm[mt][ng*2 + 1], ah[mt], bm + 2);
                        mma16816(accm[mt][ng*2],     am[mt], bh);
                        mma16816(accm[mt][ng*2 + 1], am[mt], bh + 2);
                    } else {
                        mma16816(acch[mt][ng*2],     ah[mt], bh);
                        mma16816(acch[mt][ng*2 + 1], ah[mt], bh + 2);
                    }
                }
            }
        }
    }
    __syncthreads();   // stage buffers free -> reuse as transpose scratch

    float* scr = (float*)(smem + SO_STG) + w * (64*36);

    if (!MODE) {
        #pragma unroll
        for (int mt = 0; mt < 2; mt++)
            #pragma unroll
            for (int nt = 0; nt < 8; nt++)
                #pragma unroll
                for (int i = 0; i < 4; i++) {
                    int nl = nt*8 + (lane & 3)*2 + (i & 1);
                    int ml = mt*16 + (lane >> 2) + ((i >> 1) << 3);
                    scr[nl*36 + ml] = acch[mt][nt][i] + accm[mt][nt][i] * INV2048;
                }
        __syncwarp();
        #pragma unroll 4
        for (int r = 0; r < 64; r++) {
            int j = by*128 + wn + r;
            float val = scr[r*36 + lane];
            float mx = val, mn = val;
            #pragma unroll
            for (int d = 1; d < 32; d <<= 1) {
                mx = fmaxf(mx, __shfl_xor_sync(~0u, mx, d));
                mn = fminf(mn, __shfl_xor_sync(~0u, mn, d));
            }
            g_buf[(size_t)j*MM + m0 + wm + lane] = val;
            if (lane == 0) {
                atomicMax(&gmax_d[j], encf(mx));
                atomicMin(&gmin_d[j], encf(mn));
            }
        }
    } else {
        int mstart = m0 + wm;
        int nimg = mstart / HWC;
        size_t base = (size_t)nimg*(CC*HWC) + (size_t)(mstart - nimg*HWC);
        #pragma unroll
        for (int h = 0; h < 2; h++) {
            #pragma unroll
            for (int mt = 0; mt < 2; mt++)
                #pragma unroll
                for (int nt = 0; nt < 8; nt++)
                    #pragma unroll
                    for (int i = 0; i < 4; i++) {
                        int nl = nt*8 + (lane & 3)*2 + (i & 1);
                        int ml = mt*16 + (lane >> 2) + ((i >> 1) << 3);
                        scr[nl*36 + ml] = acch[mt][h*8 + nt][i] * INV1024;
                    }
            __syncwarp();
            #pragma unroll 4
            for (int r = 0; r < 64; r++) {
                int c = wn + h*64 + r;
                OUT[base + (size_t)c*HWC + lane] = scr[r*36 + lane] + ps[1024 + c];
            }
            __syncwarp();
        }
    }
}

// -------------------- mid: mn, s, clip, quant params --------------------
__global__ void mid_k(const float* __restrict__ u, const float* __restrict__ cv,
                      const int* __restrict__ abw) {
    __shared__ float mns[CC];
    int t = threadIdx.x;
    float mn = chsum_d[t] * (1.0f / (float)MM);
    mn_d[t] = mn; mns[t] = mn;
    __syncthreads();
    float s = 0.0f;
    #pragma unroll 8
    for (int c = 0; c < CC; c++) s += u[(size_t)c*CC + t] * mns[c];
    s_d[t] = s;
    float c = cv[t]; cvv_d[t] = c;
    int ab = abw ? *abw : 8;
    float dmax = fminf(fmaxf(decf(gmax_d[t]) - s, -c), c);
    float dmin = fminf(fmaxf(decf(gmin_d[t]) - s, -c), c);
    int same = (dmax == dmin) || (ab >= 17);
    float rng = same ? 1.0f : (dmax - dmin);
    float levels = (float)((1 << (same ? 8 : ab)) - 1);
    same_d[t]  = same ? 1.0f : 0.0f;
    dmin_d[t]  = dmin;
    scale_d[t] = levels / rng;
    inv_d[t]   = rng / levels;
}

// -------------------- wsplit: w1024 = fp16(u*iv*1024) --------------------
__global__ void wsplit_k(const float* __restrict__ u) {
    int c = blockIdx.x, j = threadIdx.x;
    float wv = u[(size_t)c*CC + j] * inv_d[j] * 1024.0f;
    w_hi_d[c*CC + j] = __float2half_rn(wv);
}

// -------------------- qsum: MLP-4 quant reduction (folded form, matches GEMM2) ----
__global__ void __launch_bounds__(128) qsum_k() {
    __shared__ float red[4];
    int j = blockIdx.y;
    float s = s_d[j], dm = dmin_d[j], sc = scale_d[j], iv = inv_d[j],
          cv = cvv_d[j], smf = same_d[j];
    float NC = -(s + dm) * sc;
    float LO = (-cv - dm) * sc;
    float HI = (cv - dm) * sc;
    size_t base = (size_t)j*MM + (size_t)blockIdx.x*2048 + threadIdx.x*4;
    float4 v0 = *(const float4*)(g_buf + base);
    float4 v1 = *(const float4*)(g_buf + base + 512);
    float4 v2 = *(const float4*)(g_buf + base + 1024);
    float4 v3 = *(const float4*)(g_buf + base + 1536);
    float gg[16] = { v0.x,v0.y,v0.z,v0.w, v1.x,v1.y,v1.z,v1.w,
                     v2.x,v2.y,v2.z,v2.w, v3.x,v3.y,v3.z,v3.w };
    float sum = 0.f;
    #pragma unroll
    for (int i = 0; i < 16; i++) {
        float q;
        if (smf > 0.5f) q = fminf(fmaxf(gg[i] - s, -cv), cv);       // same: unquantized val
        else            q = fmaf(qlevel(gg[i], sc, NC, LO, HI), iv, dm);
        sum += q;
    }
    #pragma unroll
    for (int d = 1; d < 32; d <<= 1) sum += __shfl_xor_sync(~0u, sum, d);
    int lane = threadIdx.x & 31, wid = threadIdx.x >> 5;
    if (lane == 0) red[wid] = sum;
    __syncthreads();
    if (threadIdx.x == 0)
        atomicAdd(&qsum_d[j], red[0] + red[1] + red[2] + red[3]);
}

// -------------------- bias2[c] = mn[c] + sum_j u[c][j]*(dmin[j] - qmean[j]) ----
__global__ void bias_k(const float* __restrict__ u) {
    __shared__ float dq[CC];
    int t = threadIdx.x;
    dq[t] = dmin_d[t] - qsum_d[t] * (1.0f / (float)MM);
    __syncthreads();
    float b = 0.0f;
    #pragma unroll 8
    for (int j = 0; j < CC; j++) b += u[(size_t)t*CC + j] * dq[j];
    bias_d[t] = mn_d[t] + b;
}

// -------------------- launcher --------------------
extern "C" void kernel_launch(void* const* d_in, const int* in_sizes, int n_in,
                              void* d_out, int out_size) {
    const float* x  = (const float*)d_in[0];
    const float* u  = (const float*)d_in[1];
    const float* cv = (const float*)d_in[2];
    const int*   ab = (n_in > 3) ? (const int*)d_in[3] : nullptr;
    float* out = (float*)d_out;
    (void)in_sizes; (void)out_size;

    cudaFuncSetAttribute(mgemm_k<0>, cudaFuncAttributeMaxDynamicSharedMemorySize, SMEM_T);
    cudaFuncSetAttribute(mgemm_k<1>, cudaFuncAttributeMaxDynamicSharedMemorySize, SMEM_T);

    prep_k<<<CC + 1, CC>>>(u);
    mgemm_k<0><<<dim3(2, NTILE), NTH, SMEM_T>>>(x, nullptr);     // n-half adjacent -> L2 dedup
    mid_k<<<1, CC>>>(u, cv, ab);
    wsplit_k<<<CC, CC>>>(u);
    qsum_k<<<dim3(49, CC), 128>>>();
    bias_k<<<1, CC>>>(u);
    mgemm_k<1><<<dim3(NTILE, 1), NTH, SMEM_T>>>(nullptr, out);   // full-N per CTA
}

// round 14
// speedup vs baseline: 1.4090x; 1.0364x over previous
#include <cuda_runtime.h>
#include <cuda_fp16.h>
#include <cstdint>

#define CC 256
#define HWC 3136
#define MM 100352
#define NTILE 784
#define NTH 256
#define STRA 40                 /* halfs per smem row (80B, conflict-free ldmatrix) */
/* MODE0 stage: AH 10240 | AM 10240 | BH 10240 | BM 10240  (40960) */
#define STG_AH 0
#define STG_AM 10240
#define STG_BH 20480
#define STG_BM 30720
#define STG_SZ0 40960
#define STG_B1 10240
#define STG_SZ1 30720
#define SO_STG 8192
#define SMEM_T (SO_STG + 2*STG_SZ0)   /* 90112 */
/* GEMM2 (64-row tile): ps 5KB | stage A 5120 + B 20480 = 25600 x2 | scr 73728 */
#define G2_STG 25600
#define G2_B   5120
#define SMEM2  (SO_STG + 73728)       /* 81920 */
#define INV2048 (1.0f/2048.0f)
#define INV1024 (1.0f/1024.0f)
#define QBLOCKS (49*256)

// -------------------- device scratch --------------------
__device__ __align__(16) float  g_buf[(size_t)CC*MM];
__device__ __align__(16) __half ut_hi_d[CC*CC], ut_mid_d[CC*CC];   // GEMM1 B [j][c]
__device__ __align__(16) __half w_hi_d[CC*CC];                     // GEMM2 B [c][j] = fp16(u*iv*1024)
__device__ float    chsum_d[CC];
__device__ unsigned gmax_d[CC], gmin_d[CC];
__device__ float    mn_d[CC], s_d[CC], dmin_d[CC], scale_d[CC], inv_d[CC], cvv_d[CC];
__device__ float    qsum_d[CC], bias_d[CC], same_d[CC];
__device__ unsigned qcnt_d;

// -------------------- helpers --------------------
__device__ __forceinline__ void cp16(uint32_t sdst, const void* g) {
    asm volatile("cp.async.ca.shared.global [%0], [%1], 16;" :: "r"(sdst), "l"(g) : "memory");
}
__device__ __forceinline__ void cp_commit() { asm volatile("cp.async.commit_group;" ::: "memory"); }
__device__ __forceinline__ void cp_wait0()  { asm volatile("cp.async.wait_group 0;" ::: "memory"); }

__device__ __forceinline__ void ldsm4(unsigned* r, uint32_t addr) {
    asm volatile("ldmatrix.sync.aligned.m8n8.x4.shared.b16 {%0,%1,%2,%3}, [%4];"
        : "=r"(r[0]), "=r"(r[1]), "=r"(r[2]), "=r"(r[3]) : "r"(addr));
}
__device__ __forceinline__ void mma16816(float* d, const unsigned* a, const unsigned* b) {
    asm volatile("mma.sync.aligned.m16n8k16.row.col.f32.f16.f16.f32 "
        "{%0,%1,%2,%3}, {%4,%5,%6,%7}, {%8,%9}, {%0,%1,%2,%3};"
        : "+f"(d[0]), "+f"(d[1]), "+f"(d[2]), "+f"(d[3])
        : "r"(a[0]), "r"(a[1]), "r"(a[2]), "r"(a[3]), "r"(b[0]), "r"(b[1]));
}
__device__ __forceinline__ unsigned encf(float f) {
    unsigned u = __float_as_uint(f);
    return (u & 0x80000000u) ? ~u : (u | 0x80000000u);
}
__device__ __forceinline__ float decf(unsigned u) {
    unsigned b = (u & 0x80000000u) ? (u & 0x7FFFFFFFu) : ~u;
    return __uint_as_float(b);
}
// folded quantizer (identical in qsum_k and GEMM2 producer):
__device__ __forceinline__ float qlevel(float g, float sc, float negC, float lo, float hi) {
    return rintf(fminf(fmaxf(fmaf(g, sc, negC), lo), hi));
}

// -------------------- prep --------------------
__global__ void prep_k(const float* __restrict__ u) {
    int t = threadIdx.x, b = blockIdx.x;
    if (b < CC) {
        float val = u[(size_t)b*CC + t];          // u[c=b][j=t]
        __half h = __float2half_rn(val);
        __half e = __float2half_rn((val - __half2float(h)) * 2048.0f);
        ut_hi_d[t*CC + b] = h;  ut_mid_d[t*CC + b] = e;   // [j][c] for GEMM1 B
    } else {
        chsum_d[t] = 0.0f; qsum_d[t] = 0.0f;
        gmax_d[t] = 0u; gmin_d[t] = 0xFFFFFFFFu;
        if (t == 0) qcnt_d = 0u;
    }
}

// -------------------- GEMM1 (unchanged R13 path, MODE 0 only) --------------------
template<int MODE>
__global__ void __launch_bounds__(NTH)
mgemm_k(const float* __restrict__ X, float* __restrict__ OUT)
{
    extern __shared__ char smem[];
    const uint32_t sb = (uint32_t)__cvta_generic_to_shared(smem);
    const int tid = threadIdx.x;
    const int lane = tid & 31, w = tid >> 5;
    const int m0 = blockIdx.y * 128;
    const int by = blockIdx.x;                  // n-half
    const int STGSZ = STG_SZ0;

    const int mg = tid & 15, cp = tid >> 4;     // producer coords: 8-m group, k-pair
    const int mrow = m0 + mg*8;
    int nimg0 = mrow / HWC;
    size_t abase = (size_t)nimg0*(CC*HWC) + (size_t)(mrow - nimg0*HWC);

    float v[2][8];

    auto loadA = [&](int kc) {
        #pragma unroll
        for (int cc = 0; cc < 2; cc++) {
            int c = kc*32 + cp*2 + cc;
            const float4* p = (const float4*)(X + abase + (size_t)c*HWC);
            float4 q0 = p[0], q1 = p[1];
            v[cc][0]=q0.x; v[cc][1]=q0.y; v[cc][2]=q0.z; v[cc][3]=q0.w;
            v[cc][4]=q1.x; v[cc][5]=q1.y; v[cc][6]=q1.z; v[cc][7]=q1.w;
        }
    };
    auto procA = [&](int kc, int st) {
        char* base = smem + SO_STG + st*STGSZ;
        #pragma unroll
        for (int cc = 0; cc < 2; cc++) {
            int c = kc*32 + cp*2 + cc;
            float s = 0.f;
            #pragma unroll
            for (int i = 0; i < 8; i++) { v[cc][i] = fmaxf(v[cc][i], 0.f); s += v[cc][i]; }
            s += __shfl_xor_sync(~0u, s, 1); s += __shfl_xor_sync(~0u, s, 2);
            s += __shfl_xor_sync(~0u, s, 4); s += __shfl_xor_sync(~0u, s, 8);
            if (by == 0 && (lane & 15) == 0) atomicAdd(&chsum_d[c], s);
        }
        #pragma unroll
        for (int i = 0; i < 8; i++) {
            __half h0 = __float2half_rn(v[0][i]);
            __half h1 = __float2half_rn(v[1][i]);
            __half e0 = __float2half_rn((v[0][i] - __half2float(h0)) * 2048.0f);
            __half e1 = __float2half_rn((v[1][i] - __half2float(h1)) * 2048.0f);
            uint32_t off = (uint32_t)(((mg*8 + i)*STRA + cp*2) * 2);
            *(__half2*)(base + STG_AH + off) = __halves2half2(h0, h1);
            *(__half2*)(base + STG_AM + off) = __halves2half2(e0, e1);
        }
    };
    auto prodB = [&](int kc, int st) {
        #pragma unroll
        for (int i = 0; i < 4; i++) {
            int ui = tid + i*NTH;                 // 0..1023
            int ish = (ui < 512);
            int r = (ui & 511) >> 2;              // row 0..127
            int q = ui & 3;
            uint32_t dst = sb + SO_STG + st*STGSZ + (ish ? STG_BH : STG_BM)
                         + (uint32_t)(r*80 + q*16);
            const __half* s = (ish ? ut_hi_d : ut_mid_d) + (size_t)(by*128 + r)*CC + kc*32 + q*8;
            cp16(dst, s);
        }
    };

    float acch[2][8][4] = {};
    float accm[2][8][4] = {};
    const int wm = (w & 3) * 32;
    const int wn = (w >> 2) * 64;

    loadA(0);
    procA(0, 0);
    prodB(0, 0); cp_commit();
    loadA(1);

    const int arow = (lane & 15);
    const int asel = (lane >> 4) << 3;
    const int brow = (lane & 7) + ((lane >> 4) << 3);
    const int bsel = ((lane >> 3) & 1) << 3;

    for (int kc = 0; kc < 8; kc++) {
        const int st = kc & 1;
        cp_wait0();
        __syncthreads();

        if (kc < 7) { procA(kc + 1, st ^ 1); prodB(kc + 1, st ^ 1); cp_commit(); }
        if (kc < 6) loadA(kc + 2);

        const uint32_t ahb = sb + SO_STG + st*STGSZ + STG_AH;
        const uint32_t bhb = sb + SO_STG + st*STGSZ + STG_BH;
        #pragma unroll
        for (int ks = 0; ks < 2; ks++) {
            const int kb = ks*16;
            unsigned ah[2][4], am[2][4];
            #pragma unroll
            for (int mt = 0; mt < 2; mt++) {
                uint32_t ra = ahb + (uint32_t)(((wm + mt*16 + arow)*STRA + kb + asel) * 2);
                ldsm4(ah[mt], ra);
                ldsm4(am[mt], ra + (STG_AM - STG_AH));
            }
            #pragma unroll
            for (int ng = 0; ng < 4; ng++) {
                uint32_t rb = bhb + (uint32_t)(((wn + ng*16 + brow)*STRA + kb + bsel) * 2);
                unsigned bh[4], bm[4];
                ldsm4(bh, rb);
                ldsm4(bm, rb + (STG_BM - STG_BH));
                #pragma unroll
                for (int mt = 0; mt < 2; mt++) {
                    mma16816(acch[mt][ng*2],     ah[mt], bh);
                    mma16816(acch[mt][ng*2 + 1], ah[mt], bh + 2);
                    mma16816(accm[mt][ng*2],     ah[mt], bm);
                    mma16816(accm[mt][ng*2 + 1], ah[mt], bm + 2);
                    mma16816(accm[mt][ng*2],     am[mt], bh);
                    mma16816(accm[mt][ng*2 + 1], am[mt], bh + 2);
                }
            }
        }
    }
    __syncthreads();

    float* scr = (float*)(smem + SO_STG) + w * (64*36);
    #pragma unroll
    for (int mt = 0; mt < 2; mt++)
        #pragma unroll
        for (int nt = 0; nt < 8; nt++)
            #pragma unroll
            for (int i = 0; i < 4; i++) {
                int nl = nt*8 + (lane & 3)*2 + (i & 1);
                int ml = mt*16 + (lane >> 2) + ((i >> 1) << 3);
                scr[nl*36 + ml] = acch[mt][nt][i] + accm[mt][nt][i] * INV2048;
            }
    __syncwarp();
    #pragma unroll 4
    for (int r = 0; r < 64; r++) {
        int j = by*128 + wn + r;
        float val = scr[r*36 + lane];
        float mx = val, mn = val;
        #pragma unroll
        for (int d = 1; d < 32; d <<= 1) {
            mx = fmaxf(mx, __shfl_xor_sync(~0u, mx, d));
            mn = fminf(mn, __shfl_xor_sync(~0u, mn, d));
        }
        g_buf[(size_t)j*MM + m0 + wm + lane] = val;
        if (lane == 0) {
            atomicMax(&gmax_d[j], encf(mx));
            atomicMin(&gmin_d[j], encf(mn));
        }
    }
    (void)OUT;
}

// -------------------- GEMM2: 64-row m-tile, full N, 2 CTAs/SM --------------------
// out[c][m] = (sum_j w1024[c][j]*n[j][m])/1024 + bias2[c]
__global__ void __launch_bounds__(NTH, 2)
gemm2_k(float* __restrict__ OUT)
{
    extern __shared__ char smem[];
    const uint32_t sb = (uint32_t)__cvta_generic_to_shared(smem);
    const int tid = threadIdx.x;
    const int lane = tid & 31, w = tid >> 5;
    const int m0 = blockIdx.x * 64;

    float* ps = (float*)smem;
    {
        float s  = s_d[tid], dm = dmin_d[tid], sc = scale_d[tid], cv = cvv_d[tid];
        ps[tid]        = -(s + dm) * sc;        // negC
        ps[256 + tid]  = (-cv - dm) * sc;       // lo
        ps[512 + tid]  = sc;
        ps[768 + tid]  = (cv - dm) * sc;        // hi
        ps[1024 + tid] = bias_d[tid];
    }
    __syncthreads();

    const int mg = tid & 15;       // m-group of 4 rows (16 groups x 4 = 64)
    const int cp = tid >> 4;       // c-pair 0..15
    const int mrow = m0 + mg*4;

    float v[2][4];
    auto loadA = [&](int kc) {
        #pragma unroll
        for (int cc = 0; cc < 2; cc++) {
            int c = kc*32 + cp*2 + cc;
            float4 q0 = *(const float4*)(g_buf + (size_t)c*MM + mrow);
            v[cc][0]=q0.x; v[cc][1]=q0.y; v[cc][2]=q0.z; v[cc][3]=q0.w;
        }
    };
    auto procA = [&](int kc, int st) {
        char* base = smem + SO_STG + st*G2_STG;
        #pragma unroll
        for (int cc = 0; cc < 2; cc++) {
            int c = kc*32 + cp*2 + cc;
            float NC=ps[c], LO=ps[256+c], SC=ps[512+c], HI=ps[768+c];
            #pragma unroll
            for (int i = 0; i < 4; i++)
                v[cc][i] = qlevel(v[cc][i], SC, NC, LO, HI);   // exact fp16 integer
        }
        #pragma unroll
        for (int i = 0; i < 4; i++) {
            uint32_t off = (uint32_t)(((mg*4 + i)*STRA + cp*2) * 2);
            *(__half2*)(base + off) =
                __halves2half2(__float2half_rn(v[0][i]), __float2half_rn(v[1][i]));
        }
    };
    auto prodB = [&](int kc, int st) {
        #pragma unroll
        for (int i = 0; i < 4; i++) {
            int ui = tid + i*NTH;                 // 0..1023
            int r = ui >> 2;                      // row 0..255
            int q = ui & 3;
            uint32_t dst = sb + SO_STG + st*G2_STG + G2_B + (uint32_t)(r*80 + q*16);
            cp16(dst, w_hi_d + (size_t)r*CC + kc*32 + q*8);
        }
    };

    float acc[2][8][4] = {};
    const int wm = (w & 1) * 32;
    const int wn = (w >> 1) * 64;

    loadA(0);
    procA(0, 0);
    prodB(0, 0); cp_commit();
    loadA(1);

    const int arow = (lane & 15);
    const int asel = (lane >> 4) << 3;
    const int brow = (lane & 7) + ((lane >> 4) << 3);
    const int bsel = ((lane >> 3) & 1) << 3;

    for (int kc = 0; kc < 8; kc++) {
        const int st = kc & 1;
        cp_wait0();
        __syncthreads();

        if (kc < 7) { procA(kc + 1, st ^ 1); prodB(kc + 1, st ^ 1); cp_commit(); }
        if (kc < 6) loadA(kc + 2);

        const uint32_t ahb = sb + SO_STG + st*G2_STG;
        const uint32_t bhb = ahb + G2_B;
        #pragma unroll
        for (int ks = 0; ks < 2; ks++) {
            const int kb = ks*16;
            unsigned ah[2][4];
            #pragma unroll
            for (int mt = 0; mt < 2; mt++) {
                uint32_t ra = ahb + (uint32_t)(((wm + mt*16 + arow)*STRA + kb + asel) * 2);
                ldsm4(ah[mt], ra);
            }
            #pragma unroll
            for (int ng = 0; ng < 4; ng++) {
                uint32_t rb = bhb + (uint32_t)(((wn + ng*16 + brow)*STRA + kb + bsel) * 2);
                unsigned bh[4];
                ldsm4(bh, rb);
                #pragma unroll
                for (int mt = 0; mt < 2; mt++) {
                    mma16816(acc[mt][ng*2],     ah[mt], bh);
                    mma16816(acc[mt][ng*2 + 1], ah[mt], bh + 2);
                }
            }
        }
    }
    __syncthreads();   // stage free -> scr

    float* scr = (float*)(smem + SO_STG) + w * (64*36);
    #pragma unroll
    for (int mt = 0; mt < 2; mt++)
        #pragma unroll
        for (int nt = 0; nt < 8; nt++)
            #pragma unroll
            for (int i = 0; i < 4; i++) {
                int nl = nt*8 + (lane & 3)*2 + (i & 1);
                int ml = mt*16 + (lane >> 2) + ((i >> 1) << 3);
                scr[nl*36 + ml] = acc[mt][nt][i] * INV1024;
            }
    __syncwarp();

    int mstart = m0 + wm;
    int nimg = mstart / HWC;
    size_t base = (size_t)nimg*(CC*HWC) + (size_t)(mstart - nimg*HWC);
    #pragma unroll 4
    for (int r = 0; r < 64; r++) {
        int c = wn + r;
        OUT[base + (size_t)c*HWC + lane] = scr[r*36 + lane] + ps[1024 + c];
    }
}

// -------------------- mid: quant params + fused wsplit --------------------
__global__ void mid_k(const float* __restrict__ u, const float* __restrict__ cv,
                      const int* __restrict__ abw) {
    __shared__ float mns[CC];
    __shared__ float ivs[CC];
    int t = threadIdx.x;
    float mn = chsum_d[t] * (1.0f / (float)MM);
    mn_d[t] = mn; mns[t] = mn;
    __syncthreads();
    float s = 0.0f;
    #pragma unroll 8
    for (int c = 0; c < CC; c++) s += u[(size_t)c*CC + t] * mns[c];
    s_d[t] = s;
    float c = cv[t]; cvv_d[t] = c;
    int ab = abw ? *abw : 8;
    float dmax = fminf(fmaxf(decf(gmax_d[t]) - s, -c), c);
    float dmin = fminf(fmaxf(decf(gmin_d[t]) - s, -c), c);
    int same = (dmax == dmin) || (ab >= 17);
    float rng = same ? 1.0f : (dmax - dmin);
    float levels = (float)((1 << (same ? 8 : ab)) - 1);
    same_d[t]  = same ? 1.0f : 0.0f;
    dmin_d[t]  = dmin;
    scale_d[t] = levels / rng;
    float iv = rng / levels;
    inv_d[t]   = iv;
    ivs[t] = iv * 1024.0f;
    __syncthreads();
    // fused wsplit: w1024[c][j] = fp16(u[c][j] * iv[j] * 1024)
    for (int idx = t; idx < CC*CC; idx += CC) {
        int j = idx & 255;
        w_hi_d[idx] = __float2half_rn(u[idx] * ivs[j]);
    }
}

// -------------------- qsum + fused bias (last block) --------------------
__global__ void __launch_bounds__(128) qsum_k(const float* __restrict__ u) {
    __shared__ float red[4];
    __shared__ unsigned isLast;
    int j = blockIdx.y;
    float s = s_d[j], dm = dmin_d[j], sc = scale_d[j], iv = inv_d[j],
          cv = cvv_d[j], smf = same_d[j];
    float NC = -(s + dm) * sc;
    float LO = (-cv - dm) * sc;
    float HI = (cv - dm) * sc;
    size_t base = (size_t)j*MM + (size_t)blockIdx.x*2048 + threadIdx.x*4;
    float4 v0 = *(const float4*)(g_buf + base);
    float4 v1 = *(const float4*)(g_buf + base + 512);
    float4 v2 = *(const float4*)(g_buf + base + 1024);
    float4 v3 = *(const float4*)(g_buf + base + 1536);
    float gg[16] = { v0.x,v0.y,v0.z,v0.w, v1.x,v1.y,v1.z,v1.w,
                     v2.x,v2.y,v2.z,v2.w, v3.x,v3.y,v3.z,v3.w };
    float sum = 0.f;
    #pragma unroll
    for (int i = 0; i < 16; i++) {
        float q;
        if (smf > 0.5f) q = fminf(fmaxf(gg[i] - s, -cv), cv);
        else            q = fmaf(qlevel(gg[i], sc, NC, LO, HI), iv, dm);
        sum += q;
    }
    #pragma unroll
    for (int d = 1; d < 32; d <<= 1) sum += __shfl_xor_sync(~0u, sum, d);
    int lane = threadIdx.x & 31, wid = threadIdx.x >> 5;
    if (lane == 0) red[wid] = sum;
    __syncthreads();
    if (threadIdx.x == 0) {
        atomicAdd(&qsum_d[j], red[0] + red[1] + red[2] + red[3]);
        __threadfence();
        isLast = (atomicAdd(&qcnt_d, 1u) == QBLOCKS - 1u) ? 1u : 0u;
    }
    __syncthreads();
    if (isLast) {
        // fused bias: bias[c] = mn[c] + sum_j u[c][j]*(dmin[j] - qsum[j]/MM)
        __shared__ float dq[CC];
        for (int jj = threadIdx.x; jj < CC; jj += 128)
            dq[jj] = dmin_d[jj] - qsum_d[jj] * (1.0f / (float)MM);
        __syncthreads();
        for (int c = threadIdx.x; c < CC; c += 128) {
            float b = 0.0f;
            #pragma unroll 8
            for (int jj = 0; jj < CC; jj++) b += u[(size_t)c*CC + jj] * dq[jj];
            bias_d[c] = mn_d[c] + b;
        }
    }
}

// -------------------- launcher --------------------
extern "C" void kernel_launch(void* const* d_in, const int* in_sizes, int n_in,
                              void* d_out, int out_size) {
    const float* x  = (const float*)d_in[0];
    const float* u  = (const float*)d_in[1];
    const float* cv = (const float*)d_in[2];
    const int*   ab = (n_in > 3) ? (const int*)d_in[3] : nullptr;
    float* out = (float*)d_out;
    (void)in_sizes; (void)out_size;

    cudaFuncSetAttribute(mgemm_k<0>, cudaFuncAttributeMaxDynamicSharedMemorySize, SMEM_T);
    cudaFuncSetAttribute(gemm2_k,    cudaFuncAttributeMaxDynamicSharedMemorySize, SMEM2);

    prep_k<<<CC + 1, CC>>>(u);
    mgemm_k<0><<<dim3(2, NTILE), NTH, SMEM_T>>>(x, nullptr);   // n-half adjacent -> L2 dedup
    mid_k<<<1, CC>>>(u, cv, ab);                               // + fused wsplit
    qsum_k<<<dim3(49, CC), 128>>>(u);                          // + fused bias (last block)
    gemm2_k<<<dim3(MM/64, 1), NTH, SMEM2>>>(out);              // 64-row tiles, 2 CTAs/SM
}

// round 15
// speedup vs baseline: 1.5051x; 1.0682x over previous
#include <cuda_runtime.h>
#include <cuda_fp16.h>
#include <cstdint>

#define CC 256
#define HWC 3136
#define MM 100352
#define NTH 256
#define STRA 40                 /* halfs per smem row (80B, conflict-free ldmatrix) */
/* GEMM1 (64-row m-tile): AH 5120 | AM 5120 | BH 10240 | BM 10240 = 30720/stage */
#define G1_AM 5120
#define G1_BH 10240
#define G1_BM 20480
#define G1_STG 30720
#define SO1 1024
#define SMEM1 (SO1 + 2*G1_STG)        /* 62464 -> 2 CTAs/SM */
/* GEMM2 (64-row m-tile): ps 5KB | A 5120 + B 20480 = 25600/stage */
#define G2_B   5120
#define G2_STG 25600
#define SO_STG 8192
#define SMEM2  (SO_STG + 2*G2_STG + 22528)   /* 81920 (incl. scr region) */
#define INV2048 (1.0f/2048.0f)
#define INV1024 (1.0f/1024.0f)

// -------------------- device scratch --------------------
__device__ __align__(16) float  g_buf[(size_t)CC*MM];
__device__ __align__(16) __half ut_hi_d[CC*CC], ut_mid_d[CC*CC];   // GEMM1 B [j][c]
__device__ __align__(16) __half w_hi_d[CC*CC];                     // GEMM2 B [c][j] = fp16(u*iv*1024)
__device__ float    chsum_d[CC];
__device__ unsigned gmax_d[CC], gmin_d[CC];
__device__ float    mn_d[CC], s_d[CC], dmin_d[CC], scale_d[CC], inv_d[CC], cvv_d[CC];
__device__ float    qsum_d[CC], bias_d[CC], same_d[CC];

// -------------------- helpers --------------------
__device__ __forceinline__ void cp16(uint32_t sdst, const void* g) {
    asm volatile("cp.async.ca.shared.global [%0], [%1], 16;" :: "r"(sdst), "l"(g) : "memory");
}
__device__ __forceinline__ void cp_commit() { asm volatile("cp.async.commit_group;" ::: "memory"); }
__device__ __forceinline__ void cp_wait0()  { asm volatile("cp.async.wait_group 0;" ::: "memory"); }

__device__ __forceinline__ void ldsm4(unsigned* r, uint32_t addr) {
    asm volatile("ldmatrix.sync.aligned.m8n8.x4.shared.b16 {%0,%1,%2,%3}, [%4];"
        : "=r"(r[0]), "=r"(r[1]), "=r"(r[2]), "=r"(r[3]) : "r"(addr));
}
__device__ __forceinline__ void mma16816(float* d, const unsigned* a, const unsigned* b) {
    asm volatile("mma.sync.aligned.m16n8k16.row.col.f32.f16.f16.f32 "
        "{%0,%1,%2,%3}, {%4,%5,%6,%7}, {%8,%9}, {%0,%1,%2,%3};"
        : "+f"(d[0]), "+f"(d[1]), "+f"(d[2]), "+f"(d[3])
        : "r"(a[0]), "r"(a[1]), "r"(a[2]), "r"(a[3]), "r"(b[0]), "r"(b[1]));
}
__device__ __forceinline__ unsigned encf(float f) {
    unsigned u = __float_as_uint(f);
    return (u & 0x80000000u) ? ~u : (u | 0x80000000u);
}
__device__ __forceinline__ float decf(unsigned u) {
    unsigned b = (u & 0x80000000u) ? (u & 0x7FFFFFFFu) : ~u;
    return __uint_as_float(b);
}
__device__ __forceinline__ float qlevel(float g, float sc, float negC, float lo, float hi) {
    return rintf(fminf(fmaxf(fmaf(g, sc, negC), lo), hi));
}

// -------------------- prep --------------------
__global__ void prep_k(const float* __restrict__ u) {
    int t = threadIdx.x, b = blockIdx.x;
    if (b < CC) {
        float val = u[(size_t)b*CC + t];          // u[c=b][j=t]
        __half h = __float2half_rn(val);
        __half e = __float2half_rn((val - __half2float(h)) * 2048.0f);
        ut_hi_d[t*CC + b] = h;  ut_mid_d[t*CC + b] = e;   // [j][c] for GEMM1 B
    } else {
        chsum_d[t] = 0.0f; qsum_d[t] = 0.0f;
        gmax_d[t] = 0u; gmin_d[t] = 0xFFFFFFFFu;
    }
}

// -------------------- GEMM1: g = u^T relu(x), 3-term split, 64-row tiles, 2 CTA/SM ----
__global__ void __launch_bounds__(NTH, 2)
gemm1_k(const float* __restrict__ X)
{
    extern __shared__ char smem[];
    const uint32_t sb = (uint32_t)__cvta_generic_to_shared(smem);
    const int tid = threadIdx.x;
    const int lane = tid & 31, w = tid >> 5;
    const int m0 = blockIdx.y * 64;
    const int by = blockIdx.x;                  // n-half

    const int mg = tid & 15;                    // m-group of 4 rows
    const int cp = tid >> 4;                    // c-pair 0..15
    const int mrow = m0 + mg*4;
    int nimg0 = mrow / HWC;                     // 4-m group never crosses image (3136%4==0)
    size_t abase = (size_t)nimg0*(CC*HWC) + (size_t)(mrow - nimg0*HWC);

    float v[2][4];

    auto loadA = [&](int kc) {
        #pragma unroll
        for (int cc = 0; cc < 2; cc++) {
            int c = kc*32 + cp*2 + cc;
            float4 q = *(const float4*)(X + abase + (size_t)c*HWC);
            v[cc][0]=q.x; v[cc][1]=q.y; v[cc][2]=q.z; v[cc][3]=q.w;
        }
    };
    auto procA = [&](int kc, int st) {
        char* base = smem + SO1 + st*G1_STG;
        #pragma unroll
        for (int cc = 0; cc < 2; cc++) {
            int c = kc*32 + cp*2 + cc;
            float s = 0.f;
            #pragma unroll
            for (int i = 0; i < 4; i++) { v[cc][i] = fmaxf(v[cc][i], 0.f); s += v[cc][i]; }
            s += __shfl_xor_sync(~0u, s, 1); s += __shfl_xor_sync(~0u, s, 2);
            s += __shfl_xor_sync(~0u, s, 4); s += __shfl_xor_sync(~0u, s, 8);
            if (by == 0 && (lane & 15) == 0) atomicAdd(&chsum_d[c], s);
        }
        #pragma unroll
        for (int i = 0; i < 4; i++) {
            __half h0 = __float2half_rn(v[0][i]);
            __half h1 = __float2half_rn(v[1][i]);
            __half e0 = __float2half_rn((v[0][i] - __half2float(h0)) * 2048.0f);
            __half e1 = __float2half_rn((v[1][i] - __half2float(h1)) * 2048.0f);
            uint32_t off = (uint32_t)(((mg*4 + i)*STRA + cp*2) * 2);
            *(__half2*)(base + off)        = __halves2half2(h0, h1);
            *(__half2*)(base + G1_AM + off) = __halves2half2(e0, e1);
        }
    };
    auto prodB = [&](int kc, int st) {
        #pragma unroll
        for (int i = 0; i < 4; i++) {
            int ui = tid + i*NTH;                 // 0..1023
            int ish = (ui < 512);
            int r = (ui & 511) >> 2;              // row 0..127
            int q = ui & 3;
            uint32_t dst = sb + SO1 + st*G1_STG + (ish ? G1_BH : G1_BM)
                         + (uint32_t)(r*80 + q*16);
            const __half* s = (ish ? ut_hi_d : ut_mid_d) + (size_t)(by*128 + r)*CC + kc*32 + q*8;
            cp16(dst, s);
        }
    };

    float acch[2][4][4] = {};
    float accm[2][4][4] = {};
    const int wm = (w & 1) * 32;
    const int wn = (w >> 1) * 32;

    loadA(0);
    procA(0, 0);
    prodB(0, 0); cp_commit();
    loadA(1);

    const int arow = (lane & 15);
    const int asel = (lane >> 4) << 3;
    const int brow = (lane & 7) + ((lane >> 4) << 3);
    const int bsel = ((lane >> 3) & 1) << 3;

    for (int kc = 0; kc < 8; kc++) {
        const int st = kc & 1;
        cp_wait0();
        __syncthreads();

        if (kc < 7) { procA(kc + 1, st ^ 1); prodB(kc + 1, st ^ 1); cp_commit(); }
        if (kc < 6) loadA(kc + 2);

        const uint32_t ahb = sb + SO1 + st*G1_STG;
        const uint32_t bhb = ahb + G1_BH;
        #pragma unroll
        for (int ks = 0; ks < 2; ks++) {
            const int kb = ks*16;
            unsigned ah[2][4], am[2][4];
            #pragma unroll
            for (int mt = 0; mt < 2; mt++) {
                uint32_t ra = ahb + (uint32_t)(((wm + mt*16 + arow)*STRA + kb + asel) * 2);
                ldsm4(ah[mt], ra);
                ldsm4(am[mt], ra + G1_AM);
            }
            #pragma unroll
            for (int ng = 0; ng < 2; ng++) {
                uint32_t rb = bhb + (uint32_t)(((wn + ng*16 + brow)*STRA + kb + bsel) * 2);
                unsigned bh[4], bm[4];
                ldsm4(bh, rb);
                ldsm4(bm, rb + (G1_BM - G1_BH));
                #pragma unroll
                for (int mt = 0; mt < 2; mt++) {
                    mma16816(acch[mt][ng*2],     ah[mt], bh);
                    mma16816(acch[mt][ng*2 + 1], ah[mt], bh + 2);
                    mma16816(accm[mt][ng*2],     ah[mt], bm);
                    mma16816(accm[mt][ng*2 + 1], ah[mt], bm + 2);
                    mma16816(accm[mt][ng*2],     am[mt], bh);
                    mma16816(accm[mt][ng*2 + 1], am[mt], bh + 2);
                }
            }
        }
    }
    __syncthreads();   // stage free -> scr

    float* scr = (float*)(smem + SO1) + w * (32*36);
    #pragma unroll
    for (int mt = 0; mt < 2; mt++)
        #pragma unroll
        for (int nt = 0; nt < 4; nt++)
            #pragma unroll
            for (int i = 0; i < 4; i++) {
                int nl = nt*8 + (lane & 3)*2 + (i & 1);
                int ml = mt*16 + (lane >> 2) + ((i >> 1) << 3);
                scr[nl*36 + ml] = acch[mt][nt][i] + accm[mt][nt][i] * INV2048;
            }
    __syncwarp();
    #pragma unroll 4
    for (int r = 0; r < 32; r++) {
        int j = by*128 + wn + r;
        float val = scr[r*36 + lane];
        float mx = val, mn = val;
        #pragma unroll
        for (int d = 1; d < 32; d <<= 1) {
            mx = fmaxf(mx, __shfl_xor_sync(~0u, mx, d));
            mn = fminf(mn, __shfl_xor_sync(~0u, mn, d));
        }
        g_buf[(size_t)j*MM + m0 + wm + lane] = val;
        if (lane == 0) {
            atomicMax(&gmax_d[j], encf(mx));
            atomicMin(&gmin_d[j], encf(mn));
        }
    }
}

// -------------------- GEMM2: 64-row m-tile, full N, 2 CTAs/SM (R14-proven) --------
__global__ void __launch_bounds__(NTH, 2)
gemm2_k(float* __restrict__ OUT)
{
    extern __shared__ char smem[];
    const uint32_t sb = (uint32_t)__cvta_generic_to_shared(smem);
    const int tid = threadIdx.x;
    const int lane = tid & 31, w = tid >> 5;
    const int m0 = blockIdx.x * 64;

    float* ps = (float*)smem;
    {
        float s  = s_d[tid], dm = dmin_d[tid], sc = scale_d[tid], cv = cvv_d[tid];
        ps[tid]        = -(s + dm) * sc;        // negC
        ps[256 + tid]  = (-cv - dm) * sc;       // lo
        ps[512 + tid]  = sc;
        ps[768 + tid]  = (cv - dm) * sc;        // hi
        ps[1024 + tid] = bias_d[tid];
    }
    __syncthreads();

    const int mg = tid & 15;
    const int cp = tid >> 4;
    const int mrow = m0 + mg*4;

    float v[2][4];
    auto loadA = [&](int kc) {
        #pragma unroll
        for (int cc = 0; cc < 2; cc++) {
            int c = kc*32 + cp*2 + cc;
            float4 q0 = *(const float4*)(g_buf + (size_t)c*MM + mrow);
            v[cc][0]=q0.x; v[cc][1]=q0.y; v[cc][2]=q0.z; v[cc][3]=q0.w;
        }
    };
    auto procA = [&](int kc, int st) {
        char* base = smem + SO_STG + st*G2_STG;
        #pragma unroll
        for (int cc = 0; cc < 2; cc++) {
            int c = kc*32 + cp*2 + cc;
            float NC=ps[c], LO=ps[256+c], SC=ps[512+c], HI=ps[768+c];
            #pragma unroll
            for (int i = 0; i < 4; i++)
                v[cc][i] = qlevel(v[cc][i], SC, NC, LO, HI);
        }
        #pragma unroll
        for (int i = 0; i < 4; i++) {
            uint32_t off = (uint32_t)(((mg*4 + i)*STRA + cp*2) * 2);
            *(__half2*)(base + off) =
                __halves2half2(__float2half_rn(v[0][i]), __float2half_rn(v[1][i]));
        }
    };
    auto prodB = [&](int kc, int st) {
        #pragma unroll
        for (int i = 0; i < 4; i++) {
            int ui = tid + i*NTH;                 // 0..1023
            int r = ui >> 2;                      // row 0..255
            int q = ui & 3;
            uint32_t dst = sb + SO_STG + st*G2_STG + G2_B + (uint32_t)(r*80 + q*16);
            cp16(dst, w_hi_d + (size_t)r*CC + kc*32 + q*8);
        }
    };

    float acc[2][8][4] = {};
    const int wm = (w & 1) * 32;
    const int wn = (w >> 1) * 64;

    loadA(0);
    procA(0, 0);
    prodB(0, 0); cp_commit();
    loadA(1);

    const int arow = (lane & 15);
    const int asel = (lane >> 4) << 3;
    const int brow = (lane & 7) + ((lane >> 4) << 3);
    const int bsel = ((lane >> 3) & 1) << 3;

    for (int kc = 0; kc < 8; kc++) {
        const int st = kc & 1;
        cp_wait0();
        __syncthreads();

        if (kc < 7) { procA(kc + 1, st ^ 1); prodB(kc + 1, st ^ 1); cp_commit(); }
        if (kc < 6) loadA(kc + 2);

        const uint32_t ahb = sb + SO_STG + st*G2_STG;
        const uint32_t bhb = ahb + G2_B;
        #pragma unroll
        for (int ks = 0; ks < 2; ks++) {
            const int kb = ks*16;
            unsigned ah[2][4];
            #pragma unroll
            for (int mt = 0; mt < 2; mt++) {
                uint32_t ra = ahb + (uint32_t)(((wm + mt*16 + arow)*STRA + kb + asel) * 2);
                ldsm4(ah[mt], ra);
            }
            #pragma unroll
            for (int ng = 0; ng < 4; ng++) {
                uint32_t rb = bhb + (uint32_t)(((wn + ng*16 + brow)*STRA + kb + bsel) * 2);
                unsigned bh[4];
                ldsm4(bh, rb);
                #pragma unroll
                for (int mt = 0; mt < 2; mt++) {
                    mma16816(acc[mt][ng*2],     ah[mt], bh);
                    mma16816(acc[mt][ng*2 + 1], ah[mt], bh + 2);
                }
            }
        }
    }
    __syncthreads();   // stage free -> scr

    float* scr = (float*)(smem + SO_STG) + w * (64*36);
    #pragma unroll
    for (int mt = 0; mt < 2; mt++)
        #pragma unroll
        for (int nt = 0; nt < 8; nt++)
            #pragma unroll
            for (int i = 0; i < 4; i++) {
                int nl = nt*8 + (lane & 3)*2 + (i & 1);
                int ml = mt*16 + (lane >> 2) + ((i >> 1) << 3);
                scr[nl*36 + ml] = acc[mt][nt][i] * INV1024;
            }
    __syncwarp();

    int mstart = m0 + wm;
    int nimg = mstart / HWC;
    size_t base = (size_t)nimg*(CC*HWC) + (size_t)(mstart - nimg*HWC);
    #pragma unroll 4
    for (int r = 0; r < 64; r++) {
        int c = wn + r;
        OUT[base + (size_t)c*HWC + lane] = scr[r*36 + lane] + ps[1024 + c];
    }
}

// -------------------- mid: quant params + fused wsplit (R14-proven) --------------------
__global__ void mid_k(const float* __restrict__ u, const float* __restrict__ cv,
                      const int* __restrict__ abw) {
    __shared__ float mns[CC];
    __shared__ float ivs[CC];
    int t = threadIdx.x;
    float mn = chsum_d[t] * (1.0f / (float)MM);
    mn_d[t] = mn; mns[t] = mn;
    __syncthreads();
    float s = 0.0f;
    #pragma unroll 8
    for (int c = 0; c < CC; c++) s += u[(size_t)c*CC + t] * mns[c];
    s_d[t] = s;
    float c = cv[t]; cvv_d[t] = c;
    int ab = abw ? *abw : 8;
    float dmax = fminf(fmaxf(decf(gmax_d[t]) - s, -c), c);
    float dmin = fminf(fmaxf(decf(gmin_d[t]) - s, -c), c);
    int same = (dmax == dmin) || (ab >= 17);
    float rng = same ? 1.0f : (dmax - dmin);
    float levels = (float)((1 << (same ? 8 : ab)) - 1);
    same_d[t]  = same ? 1.0f : 0.0f;
    dmin_d[t]  = dmin;
    scale_d[t] = levels / rng;
    float iv = rng / levels;
    inv_d[t]   = iv;
    ivs[t] = iv * 1024.0f;
    __syncthreads();
    for (int idx = t; idx < CC*CC; idx += CC) {
        int j = idx & 255;
        w_hi_d[idx] = __float2half_rn(u[idx] * ivs[j]);
    }
}

// -------------------- qsum: 512-thread (R5-proven shape), folded math --------------------
__global__ void __launch_bounds__(512, 2) qsum_k() {
    __shared__ float red[16];
    int j = blockIdx.y;
    float s = s_d[j], dm = dmin_d[j], sc = scale_d[j], iv = inv_d[j],
          cv = cvv_d[j], smf = same_d[j];
    float NC = -(s + dm) * sc;
    float LO = (-cv - dm) * sc;
    float HI = (cv - dm) * sc;
    size_t base = (size_t)j*MM + (size_t)blockIdx.x*2048 + threadIdx.x*4;
    float4 vv = *(const float4*)(g_buf + base);
    float gg[4] = { vv.x, vv.y, vv.z, vv.w };
    float sum = 0.f;
    #pragma unroll
    for (int i = 0; i < 4; i++) {
        float q;
        if (smf > 0.5f) q = fminf(fmaxf(gg[i] - s, -cv), cv);
        else            q = fmaf(qlevel(gg[i], sc, NC, LO, HI), iv, dm);
        sum += q;
    }
    #pragma unroll
    for (int d = 1; d < 32; d <<= 1) sum += __shfl_xor_sync(~0u, sum, d);
    int lane = threadIdx.x & 31, wid = threadIdx.x >> 5;
    if (lane == 0) red[wid] = sum;
    __syncthreads();
    if (threadIdx.x < 16) {
        float r = red[threadIdx.x];
        #pragma unroll
        for (int d = 1; d < 16; d <<= 1) r += __shfl_xor_sync(0xffffu, r, d);
        if (threadIdx.x == 0) atomicAdd(&qsum_d[j], r);
    }
}

// -------------------- bias2[c] = mn[c] + sum_j u[c][j]*(dmin[j] - qmean[j]) ----
__global__ void bias_k(const float* __restrict__ u) {
    __shared__ float dq[CC];
    int t = threadIdx.x;
    dq[t] = dmin_d[t] - qsum_d[t] * (1.0f / (float)MM);
    __syncthreads();
    float b = 0.0f;
    #pragma unroll 8
    for (int j = 0; j < CC; j++) b += u[(size_t)t*CC + j] * dq[j];
    bias_d[t] = mn_d[t] + b;
}

// -------------------- launcher --------------------
extern "C" void kernel_launch(void* const* d_in, const int* in_sizes, int n_in,
                              void* d_out, int out_size) {
    const float* x  = (const float*)d_in[0];
    const float* u  = (const float*)d_in[1];
    const float* cv = (const float*)d_in[2];
    const int*   ab = (n_in > 3) ? (const int*)d_in[3] : nullptr;
    float* out = (float*)d_out;
    (void)in_sizes; (void)out_size;

    cudaFuncSetAttribute(gemm1_k, cudaFuncAttributeMaxDynamicSharedMemorySize, SMEM1);
    cudaFuncSetAttribute(gemm2_k, cudaFuncAttributeMaxDynamicSharedMemorySize, SMEM2);

    prep_k<<<CC + 1, CC>>>(u);
    gemm1_k<<<dim3(2, MM/64), NTH, SMEM1>>>(x);        // 64-row tiles, 2 CTAs/SM
    mid_k<<<1, CC>>>(u, cv, ab);                       // + fused wsplit
    qsum_k<<<dim3(MM/2048, CC), 512>>>();              // proven 512-thread shape
    bias_k<<<1, CC>>>(u);
    gemm2_k<<<dim3(MM/64, 1), NTH, SMEM2>>>(out);      // 64-row tiles, 2 CTAs/SM
}

// round 16
// speedup vs baseline: 1.5324x; 1.0182x over previous
#include <cuda_runtime.h>
#include <cuda_fp16.h>
#include <cstdint>

#define CC 256
#define HWC 3136
#define MM 100352
#define NTH 256
#define STRA 40                 /* halfs per smem row (80B, conflict-free ldmatrix) */
/* GEMM1 (64-row m-tile): AH 5120 | AM 5120 | BH 10240 | BM 10240 = 30720/stage */
#define G1_AM 5120
#define G1_BH 10240
#define G1_BM 20480
#define G1_STG 30720
#define SO1 1024
#define SMEM1 (SO1 + 2*G1_STG)        /* 62464 -> 2 CTAs/SM */
/* GEMM2 (64-row m-tile): ps 4KB | A 5120 + B 20480 = 25600/stage */
#define G2_B   5120
#define G2_STG 25600
#define SO_STG 8192
#define SMEM2  (SO_STG + 2*G2_STG + 22528)   /* 81920 (incl. scr region) */
#define INV2048 (1.0f/2048.0f)
#define INV1024 (1.0f/1024.0f)

// -------------------- device scratch --------------------
__device__ __align__(16) float  g_buf[(size_t)CC*MM];
__device__ __align__(16) unsigned char n_buf[(size_t)CC*MM];       // u8 quant levels
__device__ __align__(16) __half ut_hi_d[CC*CC], ut_mid_d[CC*CC];   // GEMM1 B [j][c]
__device__ __align__(16) __half w_hi_d[CC*CC];                     // GEMM2 B [c][j] = fp16(u*iv*1024)
__device__ float    chsum_d[CC];
__device__ unsigned gmax_d[CC], gmin_d[CC];
__device__ float    mn_d[CC], s_d[CC], dmin_d[CC], scale_d[CC], inv_d[CC], cvv_d[CC];
__device__ float    qsum_d[CC], bias_d[CC], same_d[CC];

// -------------------- helpers --------------------
__device__ __forceinline__ void cp16(uint32_t sdst, const void* g) {
    asm volatile("cp.async.ca.shared.global [%0], [%1], 16;" :: "r"(sdst), "l"(g) : "memory");
}
__device__ __forceinline__ void cp_commit() { asm volatile("cp.async.commit_group;" ::: "memory"); }
__device__ __forceinline__ void cp_wait0()  { asm volatile("cp.async.wait_group 0;" ::: "memory"); }

__device__ __forceinline__ void ldsm4(unsigned* r, uint32_t addr) {
    asm volatile("ldmatrix.sync.aligned.m8n8.x4.shared.b16 {%0,%1,%2,%3}, [%4];"
        : "=r"(r[0]), "=r"(r[1]), "=r"(r[2]), "=r"(r[3]) : "r"(addr));
}
__device__ __forceinline__ void mma16816(float* d, const unsigned* a, const unsigned* b) {
    asm volatile("mma.sync.aligned.m16n8k16.row.col.f32.f16.f16.f32 "
        "{%0,%1,%2,%3}, {%4,%5,%6,%7}, {%8,%9}, {%0,%1,%2,%3};"
        : "+f"(d[0]), "+f"(d[1]), "+f"(d[2]), "+f"(d[3])
        : "r"(a[0]), "r"(a[1]), "r"(a[2]), "r"(a[3]), "r"(b[0]), "r"(b[1]));
}
__device__ __forceinline__ unsigned encf(float f) {
    unsigned u = __float_as_uint(f);
    return (u & 0x80000000u) ? ~u : (u | 0x80000000u);
}
__device__ __forceinline__ float decf(unsigned u) {
    unsigned b = (u & 0x80000000u) ? (u & 0x7FFFFFFFu) : ~u;
    return __uint_as_float(b);
}
__device__ __forceinline__ float qlevel(float g, float sc, float negC, float lo, float hi) {
    return rintf(fminf(fmaxf(fmaf(g, sc, negC), lo), hi));
}

// -------------------- prep --------------------
__global__ void prep_k(const float* __restrict__ u) {
    int t = threadIdx.x, b = blockIdx.x;
    if (b < CC) {
        float val = u[(size_t)b*CC + t];          // u[c=b][j=t]
        __half h = __float2half_rn(val);
        __half e = __float2half_rn((val - __half2float(h)) * 2048.0f);
        ut_hi_d[t*CC + b] = h;  ut_mid_d[t*CC + b] = e;   // [j][c] for GEMM1 B
    } else {
        chsum_d[t] = 0.0f; qsum_d[t] = 0.0f;
        gmax_d[t] = 0u; gmin_d[t] = 0xFFFFFFFFu;
    }
}

// -------------------- GEMM1: g = u^T relu(x), 3-term split, 64-row tiles, 2 CTA/SM ----
__global__ void __launch_bounds__(NTH, 2)
gemm1_k(const float* __restrict__ X)
{
    extern __shared__ char smem[];
    const uint32_t sb = (uint32_t)__cvta_generic_to_shared(smem);
    const int tid = threadIdx.x;
    const int lane = tid & 31, w = tid >> 5;
    const int m0 = blockIdx.y * 64;
    const int by = blockIdx.x;                  // n-half

    const int mg = tid & 15;                    // m-group of 4 rows
    const int cp = tid >> 4;                    // c-pair 0..15
    const int mrow = m0 + mg*4;
    int nimg0 = mrow / HWC;
    size_t abase = (size_t)nimg0*(CC*HWC) + (size_t)(mrow - nimg0*HWC);

    float v[2][4];

    auto loadA = [&](int kc) {
        #pragma unroll
        for (int cc = 0; cc < 2; cc++) {
            int c = kc*32 + cp*2 + cc;
            float4 q = *(const float4*)(X + abase + (size_t)c*HWC);
            v[cc][0]=q.x; v[cc][1]=q.y; v[cc][2]=q.z; v[cc][3]=q.w;
        }
    };
    auto procA = [&](int kc, int st) {
        char* base = smem + SO1 + st*G1_STG;
        #pragma unroll
        for (int cc = 0; cc < 2; cc++) {
            int c = kc*32 + cp*2 + cc;
            float s = 0.f;
            #pragma unroll
            for (int i = 0; i < 4; i++) { v[cc][i] = fmaxf(v[cc][i], 0.f); s += v[cc][i]; }
            s += __shfl_xor_sync(~0u, s, 1); s += __shfl_xor_sync(~0u, s, 2);
            s += __shfl_xor_sync(~0u, s, 4); s += __shfl_xor_sync(~0u, s, 8);
            if (by == 0 && (lane & 15) == 0) atomicAdd(&chsum_d[c], s);
        }
        #pragma unroll
        for (int i = 0; i < 4; i++) {
            __half h0 = __float2half_rn(v[0][i]);
            __half h1 = __float2half_rn(v[1][i]);
            __half e0 = __float2half_rn((v[0][i] - __half2float(h0)) * 2048.0f);
            __half e1 = __float2half_rn((v[1][i] - __half2float(h1)) * 2048.0f);
            uint32_t off = (uint32_t)(((mg*4 + i)*STRA + cp*2) * 2);
            *(__half2*)(base + off)        = __halves2half2(h0, h1);
            *(__half2*)(base + G1_AM + off) = __halves2half2(e0, e1);
        }
    };
    auto prodB = [&](int kc, int st) {
        #pragma unroll
        for (int i = 0; i < 4; i++) {
            int ui = tid + i*NTH;                 // 0..1023
            int ish = (ui < 512);
            int r = (ui & 511) >> 2;              // row 0..127
            int q = ui & 3;
            uint32_t dst = sb + SO1 + st*G1_STG + (ish ? G1_BH : G1_BM)
                         + (uint32_t)(r*80 + q*16);
            const __half* s = (ish ? ut_hi_d : ut_mid_d) + (size_t)(by*128 + r)*CC + kc*32 + q*8;
            cp16(dst, s);
        }
    };

    float acch[2][4][4] = {};
    float accm[2][4][4] = {};
    const int wm = (w & 1) * 32;
    const int wn = (w >> 1) * 32;

    loadA(0);
    procA(0, 0);
    prodB(0, 0); cp_commit();
    loadA(1);

    const int arow = (lane & 15);
    const int asel = (lane >> 4) << 3;
    const int brow = (lane & 7) + ((lane >> 4) << 3);
    const int bsel = ((lane >> 3) & 1) << 3;

    for (int kc = 0; kc < 8; kc++) {
        const int st = kc & 1;
        cp_wait0();
        __syncthreads();

        if (kc < 7) { procA(kc + 1, st ^ 1); prodB(kc + 1, st ^ 1); cp_commit(); }
        if (kc < 6) loadA(kc + 2);

        const uint32_t ahb = sb + SO1 + st*G1_STG;
        const uint32_t bhb = ahb + G1_BH;
        #pragma unroll
        for (int ks = 0; ks < 2; ks++) {
            const int kb = ks*16;
            unsigned ah[2][4], am[2][4];
            #pragma unroll
            for (int mt = 0; mt < 2; mt++) {
                uint32_t ra = ahb + (uint32_t)(((wm + mt*16 + arow)*STRA + kb + asel) * 2);
                ldsm4(ah[mt], ra);
                ldsm4(am[mt], ra + G1_AM);
            }
            #pragma unroll
            for (int ng = 0; ng < 2; ng++) {
                uint32_t rb = bhb + (uint32_t)(((wn + ng*16 + brow)*STRA + kb + bsel) * 2);
                unsigned bh[4], bm[4];
                ldsm4(bh, rb);
                ldsm4(bm, rb + (G1_BM - G1_BH));
                #pragma unroll
                for (int mt = 0; mt < 2; mt++) {
                    mma16816(acch[mt][ng*2],     ah[mt], bh);
                    mma16816(acch[mt][ng*2 + 1], ah[mt], bh + 2);
                    mma16816(accm[mt][ng*2],     ah[mt], bm);
                    mma16816(accm[mt][ng*2 + 1], ah[mt], bm + 2);
                    mma16816(accm[mt][ng*2],     am[mt], bh);
                    mma16816(accm[mt][ng*2 + 1], am[mt], bh + 2);
                }
            }
        }
    }
    __syncthreads();   // stage free -> scr

    float* scr = (float*)(smem + SO1) + w * (32*36);
    #pragma unroll
    for (int mt = 0; mt < 2; mt++)
        #pragma unroll
        for (int nt = 0; nt < 4; nt++)
            #pragma unroll
            for (int i = 0; i < 4; i++) {
                int nl = nt*8 + (lane & 3)*2 + (i & 1);
                int ml = mt*16 + (lane >> 2) + ((i >> 1) << 3);
                scr[nl*36 + ml] = acch[mt][nt][i] + accm[mt][nt][i] * INV2048;
            }
    __syncwarp();
    #pragma unroll 4
    for (int r = 0; r < 32; r++) {
        int j = by*128 + wn + r;
        float val = scr[r*36 + lane];
        float mx = val, mn = val;
        #pragma unroll
        for (int d = 1; d < 32; d <<= 1) {
            mx = fmaxf(mx, __shfl_xor_sync(~0u, mx, d));
            mn = fminf(mn, __shfl_xor_sync(~0u, mn, d));
        }
        g_buf[(size_t)j*MM + m0 + wm + lane] = val;
        if (lane == 0) {
            atomicMax(&gmax_d[j], encf(mx));
            atomicMin(&gmin_d[j], encf(mn));
        }
    }
}

// -------------------- GEMM2: reads u8 levels, pure convert producer --------------------
__global__ void __launch_bounds__(NTH, 2)
gemm2_k(float* __restrict__ OUT)
{
    extern __shared__ char smem[];
    const uint32_t sb = (uint32_t)__cvta_generic_to_shared(smem);
    const int tid = threadIdx.x;
    const int lane = tid & 31, w = tid >> 5;
    const int m0 = blockIdx.x * 64;

    float* ps = (float*)smem;
    ps[tid] = bias_d[tid];
    __syncthreads();

    const int mg = tid & 15;
    const int cp = tid >> 4;
    const int mrow = m0 + mg*4;

    unsigned va[2];
    auto loadA = [&](int kc) {
        #pragma unroll
        for (int cc = 0; cc < 2; cc++) {
            int c = kc*32 + cp*2 + cc;
            va[cc] = *(const unsigned*)(n_buf + (size_t)c*MM + mrow);
        }
    };
    auto procA = [&](int kc, int st) {
        char* base = smem + SO_STG + st*G2_STG;
        #pragma unroll
        for (int i = 0; i < 4; i++) {
            unsigned b0 = (va[0] >> (8*i)) & 0xFFu;
            unsigned b1 = (va[1] >> (8*i)) & 0xFFu;
            uint32_t off = (uint32_t)(((mg*4 + i)*STRA + cp*2) * 2);
            *(__half2*)(base + off) =
                __halves2half2(__ushort2half_rn((unsigned short)b0),
                               __ushort2half_rn((unsigned short)b1));
        }
    };
    auto prodB = [&](int kc, int st) {
        #pragma unroll
        for (int i = 0; i < 4; i++) {
            int ui = tid + i*NTH;                 // 0..1023
            int r = ui >> 2;                      // row 0..255
            int q = ui & 3;
            uint32_t dst = sb + SO_STG + st*G2_STG + G2_B + (uint32_t)(r*80 + q*16);
            cp16(dst, w_hi_d + (size_t)r*CC + kc*32 + q*8);
        }
    };

    float acc[2][8][4] = {};
    const int wm = (w & 1) * 32;
    const int wn = (w >> 1) * 64;

    loadA(0);
    procA(0, 0);
    prodB(0, 0); cp_commit();
    loadA(1);

    const int arow = (lane & 15);
    const int asel = (lane >> 4) << 3;
    const int brow = (lane & 7) + ((lane >> 4) << 3);
    const int bsel = ((lane >> 3) & 1) << 3;

    for (int kc = 0; kc < 8; kc++) {
        const int st = kc & 1;
        cp_wait0();
        __syncthreads();

        if (kc < 7) { procA(kc + 1, st ^ 1); prodB(kc + 1, st ^ 1); cp_commit(); }
        if (kc < 6) loadA(kc + 2);

        const uint32_t ahb = sb + SO_STG + st*G2_STG;
        const uint32_t bhb = ahb + G2_B;
        #pragma unroll
        for (int ks = 0; ks < 2; ks++) {
            const int kb = ks*16;
            unsigned ah[2][4];
            #pragma unroll
            for (int mt = 0; mt < 2; mt++) {
                uint32_t ra = ahb + (uint32_t)(((wm + mt*16 + arow)*STRA + kb + asel) * 2);
                ldsm4(ah[mt], ra);
            }
            #pragma unroll
            for (int ng = 0; ng < 4; ng++) {
                uint32_t rb = bhb + (uint32_t)(((wn + ng*16 + brow)*STRA + kb + bsel) * 2);
                unsigned bh[4];
                ldsm4(bh, rb);
                #pragma unroll
                for (int mt = 0; mt < 2; mt++) {
                    mma16816(acc[mt][ng*2],     ah[mt], bh);
                    mma16816(acc[mt][ng*2 + 1], ah[mt], bh + 2);
                }
            }
        }
    }
    __syncthreads();   // stage free -> scr

    float* scr = (float*)(smem + SO_STG) + w * (64*36);
    #pragma unroll
    for (int mt = 0; mt < 2; mt++)
        #pragma unroll
        for (int nt = 0; nt < 8; nt++)
            #pragma unroll
            for (int i = 0; i < 4; i++) {
                int nl = nt*8 + (lane & 3)*2 + (i & 1);
                int ml = mt*16 + (lane >> 2) + ((i >> 1) << 3);
                scr[nl*36 + ml] = acc[mt][nt][i] * INV1024;
            }
    __syncwarp();

    int mstart = m0 + wm;
    int nimg = mstart / HWC;
    size_t base = (size_t)nimg*(CC*HWC) + (size_t)(mstart - nimg*HWC);
    #pragma unroll 4
    for (int r = 0; r < 64; r++) {
        int c = wn + r;
        OUT[base + (size_t)c*HWC + lane] = scr[r*36 + lane] + ps[c];
    }
}

// -------------------- mid: quant params + fused wsplit --------------------
__global__ void mid_k(const float* __restrict__ u, const float* __restrict__ cv,
                      const int* __restrict__ abw) {
    __shared__ float mns[CC];
    __shared__ float ivs[CC];
    int t = threadIdx.x;
    float mn = chsum_d[t] * (1.0f / (float)MM);
    mn_d[t] = mn; mns[t] = mn;
    __syncthreads();
    float s = 0.0f;
    #pragma unroll 8
    for (int c = 0; c < CC; c++) s += u[(size_t)c*CC + t] * mns[c];
    s_d[t] = s;
    float c = cv[t]; cvv_d[t] = c;
    int ab = abw ? *abw : 8;
    float dmax = fminf(fmaxf(decf(gmax_d[t]) - s, -c), c);
    float dmin = fminf(fmaxf(decf(gmin_d[t]) - s, -c), c);
    int same = (dmax == dmin) || (ab >= 17);
    float rng = same ? 1.0f : (dmax - dmin);
    float levels = (float)((1 << (same ? 8 : ab)) - 1);
    same_d[t]  = same ? 1.0f : 0.0f;
    dmin_d[t]  = dmin;
    scale_d[t] = levels / rng;
    float iv = rng / levels;
    inv_d[t]   = iv;
    ivs[t] = iv * 1024.0f;
    __syncthreads();
    for (int idx = t; idx < CC*CC; idx += CC) {
        int j = idx & 255;
        w_hi_d[idx] = __float2half_rn(u[idx] * ivs[j]);
    }
}

// -------------------- qsum: compute u8 levels once, accumulate sum(n) ----------------
__global__ void __launch_bounds__(512, 2) qsum_k() {
    __shared__ float red[16];
    int j = blockIdx.y;
    float s = s_d[j], dm = dmin_d[j], sc = scale_d[j], cv = cvv_d[j];
    float NC = -(s + dm) * sc;
    float LO = (-cv - dm) * sc;
    float HI = (cv - dm) * sc;
    size_t eoff = (size_t)blockIdx.x*2048 + threadIdx.x*4;
    float4 vv = *(const float4*)(g_buf + (size_t)j*MM + eoff);
    float n0 = qlevel(vv.x, sc, NC, LO, HI);
    float n1 = qlevel(vv.y, sc, NC, LO, HI);
    float n2 = qlevel(vv.z, sc, NC, LO, HI);
    float n3 = qlevel(vv.w, sc, NC, LO, HI);
    unsigned pk = (unsigned)(int)n0 | ((unsigned)(int)n1 << 8)
                | ((unsigned)(int)n2 << 16) | ((unsigned)(int)n3 << 24);
    *(unsigned*)(n_buf + (size_t)j*MM + eoff) = pk;
    float sum = n0 + n1 + n2 + n3;
    #pragma unroll
    for (int d = 1; d < 32; d <<= 1) sum += __shfl_xor_sync(~0u, sum, d);
    int lane = threadIdx.x & 31, wid = threadIdx.x >> 5;
    if (lane == 0) red[wid] = sum;
    __syncthreads();
    if (threadIdx.x < 16) {
        float r = red[threadIdx.x];
        #pragma unroll
        for (int d = 1; d < 16; d <<= 1) r += __shfl_xor_sync(0xffffu, r, d);
        if (threadIdx.x == 0) atomicAdd(&qsum_d[j], r);
    }
}

// -------------------- bias2[c] = mn[c] - sum_j u[c][j]*iv[j]*nmean[j] ----------------
__global__ void bias_k(const float* __restrict__ u) {
    __shared__ float dq[CC];
    int t = threadIdx.x;
    dq[t] = -inv_d[t] * qsum_d[t] * (1.0f / (float)MM);
    __syncthreads();
    float b = 0.0f;
    #pragma unroll 8
    for (int j = 0; j < CC; j++) b += u[(size_t)t*CC + j] * dq[j];
    bias_d[t] = mn_d[t] + b;
}

// -------------------- launcher --------------------
extern "C" void kernel_launch(void* const* d_in, const int* in_sizes, int n_in,
                              void* d_out, int out_size) {
    const float* x  = (const float*)d_in[0];
    const float* u  = (const float*)d_in[1];
    const float* cv = (const float*)d_in[2];
    const int*   ab = (n_in > 3) ? (const int*)d_in[3] : nullptr;
    float* out = (float*)d_out;
    (void)in_sizes; (void)out_size;

    cudaFuncSetAttribute(gemm1_k, cudaFuncAttributeMaxDynamicSharedMemorySize, SMEM1);
    cudaFuncSetAttribute(gemm2_k, cudaFuncAttributeMaxDynamicSharedMemorySize, SMEM2);

    prep_k<<<CC + 1, CC>>>(u);
    gemm1_k<<<dim3(2, MM/64), NTH, SMEM1>>>(x);        // 64-row tiles, 2 CTAs/SM
    mid_k<<<1, CC>>>(u, cv, ab);                       // + fused wsplit
    qsum_k<<<dim3(MM/2048, CC), 512>>>();              // levels -> n_buf (u8) + sum(n)
    bias_k<<<1, CC>>>(u);
    gemm2_k<<<dim3(MM/64, 1), NTH, SMEM2>>>(out);      // u8 consumer, 2 CTAs/SM
}